// round 4
// baseline (speedup 1.0000x reference)
#include <cuda_runtime.h>

#define B_   4
#define S_   2048
#define D_   512
#define H_   8
#define DK_  64
#define SCALE_ 0.125f

// ---------------- scratch (static device globals; no dynamic alloc) ----------------
__device__ float g_Q[(size_t)B_*H_*S_*DK_];   // [b][h][s][dk]
__device__ float g_K[(size_t)B_*H_*S_*DK_];
__device__ float g_V[(size_t)B_*H_*S_*DK_];
__device__ float g_ctx[(size_t)B_*S_*D_];     // [b][s][h*64+dk]

// ---------------- fp32 tiled GEMM: C = A[M,K] @ Bw[K,N] ----------------
// BM=128, BN=64, BK=16, 256 threads, per-thread 8x4 register tile.
// HEADSPLIT=true stores C[m][n] to dst[((b*8+h)*2048+s)*64+dk], m=b*2048+s, n=h*64+dk.
template<bool HEADSPLIT>
__global__ __launch_bounds__(256)
void gemm_k(const float* __restrict__ A, const float* __restrict__ Bw,
            float* __restrict__ C, int M, int N, int K, int ldb, int ldc)
{
    __shared__ float As[16][132];   // transposed A tile [k][m], padded
    __shared__ float Bs[16][64];    // B tile [k][n]
    const int t  = threadIdx.x;
    const int m0 = blockIdx.y * 128;
    const int n0 = blockIdx.x * 64;
    const int tm = t >> 4;          // 0..15 -> 8 m-rows each
    const int tn = t & 15;          // 0..15 -> 4 n-cols each

    float acc[8][4];
    #pragma unroll
    for (int i = 0; i < 8; i++)
        #pragma unroll
        for (int j = 0; j < 4; j++) acc[i][j] = 0.f;

    for (int k0 = 0; k0 < K; k0 += 16) {
        // A tile 128x16 -> As[k][m]
        #pragma unroll
        for (int i = 0; i < 2; i++) {
            int m  = (t >> 2) + i * 64;
            int kq = (t & 3) << 2;
            float4 v = *(const float4*)&A[(size_t)(m0 + m) * K + k0 + kq];
            As[kq + 0][m] = v.x; As[kq + 1][m] = v.y;
            As[kq + 2][m] = v.z; As[kq + 3][m] = v.w;
        }
        // B tile 16x64
        {
            int kb = t >> 4;
            int nb = (t & 15) << 2;
            *(float4*)&Bs[kb][nb] =
                *(const float4*)&Bw[(size_t)(k0 + kb) * ldb + n0 + nb];
        }
        __syncthreads();
        #pragma unroll
        for (int k = 0; k < 16; k++) {
            float4 a0 = *(const float4*)&As[k][tm * 8];
            float4 a1 = *(const float4*)&As[k][tm * 8 + 4];
            float4 b0 = *(const float4*)&Bs[k][tn * 4];
            float av[8] = {a0.x, a0.y, a0.z, a0.w, a1.x, a1.y, a1.z, a1.w};
            float bv[4] = {b0.x, b0.y, b0.z, b0.w};
            #pragma unroll
            for (int i = 0; i < 8; i++)
                #pragma unroll
                for (int j = 0; j < 4; j++)
                    acc[i][j] += av[i] * bv[j];
        }
        __syncthreads();
    }

    #pragma unroll
    for (int i = 0; i < 8; i++) {
        int gm = m0 + tm * 8 + i;
        #pragma unroll
        for (int j = 0; j < 4; j++) {
            int gn = n0 + tn * 4 + j;
            if (HEADSPLIT) {
                int b  = gm >> 11, s = gm & 2047;
                int h  = gn >> 6,  dk = gn & 63;
                C[((size_t)((b << 3) + h) * 2048 + s) * 64 + dk] = acc[i][j];
            } else {
                C[(size_t)gm * ldc + gn] = acc[i][j];
            }
        }
    }
}

// ---------------- fused attention ----------------
// Block = (b, q-tile of 8 rows), 256 threads, loops over all 8 heads.
// Smem layout (floats):
#define SP_OFF    0            // scores/P   [8][2048]  = 16384
#define MEAN_OFF  16384        // mean acc   [8][2048]  = 16384
#define KV_OFF    32768        // Kst[64][258]=16512 or Vs[256][66]=16896
#define QST_OFF   49664        // Q^T        [64][8]    = 512
#define RED_OFF   50176        // ctx reduce [8][8][64] = 4096
#define SM_FLOATS 54272
#define SM_BYTES  (SM_FLOATS * 4)

__global__ __launch_bounds__(256)
void attn_k(const float* __restrict__ mask, float* __restrict__ mean_out)
{
    extern __shared__ float sm[];
    float* SP    = sm + SP_OFF;
    float* MEANS = sm + MEAN_OFF;
    float* KV    = sm + KV_OFF;
    float* QST   = sm + QST_OFF;
    float* RED   = sm + RED_OFF;

    const int t  = threadIdx.x;
    const int w  = t >> 5;
    const int l  = t & 31;
    const int b  = blockIdx.y;
    const int q0 = blockIdx.x * 8;

    for (int i = t; i < 8 * 2048; i += 256) MEANS[i] = 0.f;

    for (int h = 0; h < H_; h++) {
        __syncthreads();   // protect SP/RED/QST from previous iteration readers
        // Q tile -> QST[dk][qq]
        for (int i = t; i < 512; i += 256) {
            int qq = i >> 6, dk = i & 63;
            QST[dk * 8 + qq] =
                g_Q[((size_t)(b * 8 + h) * 2048 + q0 + qq) * 64 + dk];
        }

        // ---- scores: S[8][2048] in chunks of 256 keys ----
        for (int c = 0; c < 8; c++) {
            __syncthreads();   // prior compute finished reading KV
            for (int i = t; i < 256 * 64; i += 256) {
                int nl = i >> 6, dk = i & 63;
                KV[dk * 258 + nl] =
                    g_K[((size_t)(b * 8 + h) * 2048 + c * 256 + nl) * 64 + dk];
            }
            __syncthreads();
            const int nl = w * 32 + l;
            float acc[8];
            #pragma unroll
            for (int i = 0; i < 8; i++) acc[i] = 0.f;
            #pragma unroll 16
            for (int k = 0; k < 64; k++) {
                float kv  = KV[k * 258 + nl];
                float4 qa = *(const float4*)&QST[k * 8];
                float4 qb = *(const float4*)&QST[k * 8 + 4];
                acc[0] += qa.x * kv; acc[1] += qa.y * kv;
                acc[2] += qa.z * kv; acc[3] += qa.w * kv;
                acc[4] += qb.x * kv; acc[5] += qb.y * kv;
                acc[6] += qb.z * kv; acc[7] += qb.w * kv;
            }
            const int gn = c * 256 + nl;
            #pragma unroll
            for (int qq = 0; qq < 8; qq++)
                SP[qq * 2048 + gn] =
                    acc[qq] * SCALE_ + mask[(size_t)(q0 + qq) * 2048 + gn];
        }
        __syncthreads();

        // ---- softmax (warp w owns row qq=w) + mean accumulation ----
        {
            float* row = SP + w * 2048;
            float mx = -1e30f;
            for (int i = l; i < 2048; i += 32) mx = fmaxf(mx, row[i]);
            #pragma unroll
            for (int o = 16; o > 0; o >>= 1)
                mx = fmaxf(mx, __shfl_xor_sync(0xffffffffu, mx, o));
            float sum = 0.f;
            for (int i = l; i < 2048; i += 32) {
                float e = __expf(row[i] - mx);
                row[i] = e; sum += e;
            }
            #pragma unroll
            for (int o = 16; o > 0; o >>= 1)
                sum += __shfl_xor_sync(0xffffffffu, sum, o);
            float inv = 1.f / sum;
            float* mrow = MEANS + w * 2048;
            for (int i = l; i < 2048; i += 32) {
                float p = row[i] * inv;
                row[i] = p;
                mrow[i] += p;
            }
        }
        __syncthreads();

        // ---- ctx = P @ V : warp w covers k in [c*256+32w, +32), lane l -> d {2l,2l+1} ----
        float acc2[16];
        #pragma unroll
        for (int i = 0; i < 16; i++) acc2[i] = 0.f;
        for (int c = 0; c < 8; c++) {
            for (int i = t; i < 256 * 64; i += 256) {
                int nl = i >> 6, dk = i & 63;
                KV[nl * 66 + dk] =
                    g_V[((size_t)(b * 8 + h) * 2048 + c * 256 + nl) * 64 + dk];
            }
            __syncthreads();
            const int kbase = w * 32;
            #pragma unroll
            for (int kk = 0; kk < 32; kk += 4) {
                const int k = kbase + kk;
                float2 v0 = *(const float2*)&KV[(k + 0) * 66 + 2 * l];
                float2 v1 = *(const float2*)&KV[(k + 1) * 66 + 2 * l];
                float2 v2 = *(const float2*)&KV[(k + 2) * 66 + 2 * l];
                float2 v3 = *(const float2*)&KV[(k + 3) * 66 + 2 * l];
                #pragma unroll
                for (int qq = 0; qq < 8; qq++) {
                    float4 p = *(const float4*)&SP[qq * 2048 + c * 256 + k];
                    acc2[qq * 2 + 0] += p.x * v0.x + p.y * v1.x + p.z * v2.x + p.w * v3.x;
                    acc2[qq * 2 + 1] += p.x * v0.y + p.y * v1.y + p.z * v2.y + p.w * v3.y;
                }
            }
            __syncthreads();
        }
        // cross-warp reduce of ctx partials
        #pragma unroll
        for (int qq = 0; qq < 8; qq++) {
            RED[(w * 8 + qq) * 64 + 2 * l]     = acc2[qq * 2 + 0];
            RED[(w * 8 + qq) * 64 + 2 * l + 1] = acc2[qq * 2 + 1];
        }
        __syncthreads();
        for (int o = t; o < 512; o += 256) {
            int qq = o >> 6, d = o & 63;
            float s = 0.f;
            #pragma unroll
            for (int ww = 0; ww < 8; ww++) s += RED[(ww * 8 + qq) * 64 + d];
            g_ctx[((size_t)(b * 2048 + q0 + qq)) * 512 + h * 64 + d] = s;
        }
    }
    __syncthreads();
    // ---- write attn.mean(h) ----
    for (int i = t; i < 8 * 2048; i += 256) {
        int qq = i >> 11, k = i & 2047;
        mean_out[((size_t)(b * 2048 + q0 + qq)) * 2048 + k] = MEANS[i] * 0.125f;
    }
}

// ---------------- launch ----------------
extern "C" void kernel_launch(void* const* d_in, const int* in_sizes, int n_in,
                              void* d_out, int out_size)
{
    const float* Zq   = (const float*)d_in[0];
    const float* Zkv  = (const float*)d_in[1];
    const float* mask = (const float*)d_in[2];
    const float* Wqkv = (const float*)d_in[3];
    const float* Wout = (const float*)d_in[4];
    float* out   = (float*)d_out;
    float* meanp = out + (size_t)B_ * S_ * D_;

    float *Qp, *Kp, *Vp, *Cp;
    cudaGetSymbolAddress((void**)&Qp, g_Q);
    cudaGetSymbolAddress((void**)&Kp, g_K);
    cudaGetSymbolAddress((void**)&Vp, g_V);
    cudaGetSymbolAddress((void**)&Cp, g_ctx);

    cudaFuncSetAttribute(attn_k, cudaFuncAttributeMaxDynamicSharedMemorySize,
                         SM_BYTES);

    const int M = B_ * S_;                  // 8192
    dim3 gProj(D_ / 64, M / 128);           // (8, 64)

    // Q/K/V projections (head-split stores)
    gemm_k<true><<<gProj, 256>>>(Zq,  Wqkv,        Qp, M, D_, D_, 3 * D_, 0);
    gemm_k<true><<<gProj, 256>>>(Zkv, Wqkv + D_,   Kp, M, D_, D_, 3 * D_, 0);
    gemm_k<true><<<gProj, 256>>>(Zkv, Wqkv + 2*D_, Vp, M, D_, D_, 3 * D_, 0);

    // fused attention (scores, softmax, mean, P@V)
    attn_k<<<dim3(S_ / 8, B_), 256, SM_BYTES>>>(mask, meanp);

    // out = ctx @ Wout
    gemm_k<false><<<gProj, 256>>>(Cp, Wout, out, M, D_, D_, D_, D_);
}

// round 5
// speedup vs baseline: 3.0171x; 3.0171x over previous
#include <cuda_runtime.h>

#define B_   4
#define S_   2048
#define D_   512
#define H_   8
#define DK_  64
#define SCALE_ 0.125f

// ---------------- scratch (static device globals; no dynamic alloc) ----------------
__device__ float g_Q[(size_t)B_*H_*S_*DK_];          // [b][h][s][dk]
__device__ float g_K[(size_t)B_*H_*S_*DK_];
__device__ float g_V[(size_t)B_*H_*S_*DK_];
__device__ float g_ctx[(size_t)B_*S_*D_];            // [b][s][h*64+dk]
__device__ float g_P[(size_t)B_*H_*S_*S_];           // [b][h][q][k]  (scores -> probs)

// ---------------- helpers ----------------
__device__ __forceinline__ void headsplit_store(float* dst, int gm, int gn, float v)
{
    int b = gm >> 11, s = gm & 2047;
    int h = gn >> 6,  dk = gn & 63;
    dst[((size_t)((b << 3) + h) * 2048 + s) * 64 + dk] = v;
}

// ---------------- fp32 pipelined GEMM (NN): C = A[M,K] @ Bw[K,N] ----------------
// BM=128, BK=16, 256 threads. BN=128 -> 8x8/thread; BN=64 -> 8x4/thread.
// MODE 0: plain store (ldc)
// MODE 1: headsplit to C           (N=512  : proj Q)
// MODE 2: headsplit to C / C2      (N=1024 : proj K|V)
// MODE 3: batched PV: z=bh; A=P(+bh), Bw=V(+bh), C=ctx + b*2048*512 + h*64, ldc=512
template<int BN, int MODE>
__global__ __launch_bounds__(256)
void gemm_nn(const float* __restrict__ A, const float* __restrict__ Bw,
             float* __restrict__ C, float* __restrict__ C2,
             int M, int N, int K, int lda, int ldb, int ldc)
{
    constexpr int TN   = BN / 16;             // 8 or 4
    constexpr int NBLD = (16 * BN) / (256*4); // float4/thread for B tile: 2 or 1
    constexpr int BRP  = (BN == 128) ? 8 : 16;

    __shared__ float As[16][132];
    __shared__ float Bs[16][BN];

    const int t = threadIdx.x;
    if (MODE == 3) {
        int bh = blockIdx.z, b = bh >> 3, h = bh & 7;
        A  += (size_t)bh * 2048 * 2048;
        Bw += (size_t)bh * 2048 * 64;
        C  += (size_t)b * 2048 * 512 + h * 64;
    }
    const int m0 = blockIdx.y * 128;
    const int n0 = blockIdx.x * BN;
    const int tm = t >> 4;
    const int tn = t & 15;

    const int ar = t >> 2;            // 0..63
    const int ac = (t & 3) << 2;      // 0,4,8,12
    const int br = t / (BN / 4);      // 0..BRP-1
    const int bc = (t % (BN / 4)) * 4;

    float4 pa[2], pb[NBLD];
    #pragma unroll
    for (int i = 0; i < 2; i++)
        pa[i] = *(const float4*)&A[(size_t)(m0 + ar + i*64) * lda + ac];
    #pragma unroll
    for (int i = 0; i < NBLD; i++)
        pb[i] = *(const float4*)&Bw[(size_t)(br + i*BRP) * ldb + n0 + bc];

    float acc[8][TN];
    #pragma unroll
    for (int i = 0; i < 8; i++)
        #pragma unroll
        for (int j = 0; j < TN; j++) acc[i][j] = 0.f;

    int k0 = 0;
    while (true) {
        #pragma unroll
        for (int i = 0; i < 2; i++) {
            As[ac + 0][ar + i*64] = pa[i].x; As[ac + 1][ar + i*64] = pa[i].y;
            As[ac + 2][ar + i*64] = pa[i].z; As[ac + 3][ar + i*64] = pa[i].w;
        }
        #pragma unroll
        for (int i = 0; i < NBLD; i++)
            *(float4*)&Bs[br + i*BRP][bc] = pb[i];
        __syncthreads();

        int kn = k0 + 16;
        bool more = (kn < K);
        if (more) {
            #pragma unroll
            for (int i = 0; i < 2; i++)
                pa[i] = *(const float4*)&A[(size_t)(m0 + ar + i*64) * lda + kn + ac];
            #pragma unroll
            for (int i = 0; i < NBLD; i++)
                pb[i] = *(const float4*)&Bw[(size_t)(kn + br + i*BRP) * ldb + n0 + bc];
        }

        #pragma unroll
        for (int k = 0; k < 16; k++) {
            float4 a0 = *(const float4*)&As[k][tm * 8];
            float4 a1 = *(const float4*)&As[k][tm * 8 + 4];
            float av[8] = {a0.x, a0.y, a0.z, a0.w, a1.x, a1.y, a1.z, a1.w};
            float bv[TN];
            #pragma unroll
            for (int j = 0; j < TN; j += 4) {
                float4 bq = *(const float4*)&Bs[k][tn * TN + j];
                bv[j] = bq.x; bv[j+1] = bq.y; bv[j+2] = bq.z; bv[j+3] = bq.w;
            }
            #pragma unroll
            for (int i = 0; i < 8; i++)
                #pragma unroll
                for (int j = 0; j < TN; j++)
                    acc[i][j] += av[i] * bv[j];
        }
        if (!more) break;
        __syncthreads();
        k0 = kn;
    }

    #pragma unroll
    for (int i = 0; i < 8; i++) {
        int gm = m0 + tm * 8 + i;
        #pragma unroll
        for (int j = 0; j < TN; j++) {
            int gn = n0 + tn * TN + j;
            if (MODE == 1)      headsplit_store(C, gm, gn, acc[i][j]);
            else if (MODE == 2) {
                if (gn < 512) headsplit_store(C,  gm, gn,        acc[i][j]);
                else          headsplit_store(C2, gm, gn - 512,  acc[i][j]);
            } else {
                C[(size_t)gm * ldc + gn] = acc[i][j];
            }
        }
    }
}

// ---------------- batched NT GEMM: scores = Q @ K^T * scale ----------------
// z = bh. A = Q[bh] [2048][64], B = K[bh] [2048][64], C = P[bh] [2048][2048].
__global__ __launch_bounds__(256)
void gemm_nt_scores(const float* __restrict__ Q, const float* __restrict__ Km,
                    float* __restrict__ P)
{
    __shared__ float As[16][132];
    __shared__ float Bs[16][132];

    const int t  = threadIdx.x;
    const int bh = blockIdx.z;
    const float* A  = Q  + (size_t)bh * 2048 * 64;
    const float* Bm = Km + (size_t)bh * 2048 * 64;
    float*       C  = P  + (size_t)bh * 2048 * 2048;

    const int m0 = blockIdx.y * 128;
    const int n0 = blockIdx.x * 128;
    const int tm = t >> 4;
    const int tn = t & 15;
    const int ar = t >> 2;
    const int ac = (t & 3) << 2;

    float4 pa[2], pb[2];
    #pragma unroll
    for (int i = 0; i < 2; i++) {
        pa[i] = *(const float4*)&A [(size_t)(m0 + ar + i*64) * 64 + ac];
        pb[i] = *(const float4*)&Bm[(size_t)(n0 + ar + i*64) * 64 + ac];
    }

    float acc[8][8];
    #pragma unroll
    for (int i = 0; i < 8; i++)
        #pragma unroll
        for (int j = 0; j < 8; j++) acc[i][j] = 0.f;

    int k0 = 0;
    while (true) {
        #pragma unroll
        for (int i = 0; i < 2; i++) {
            As[ac + 0][ar + i*64] = pa[i].x; As[ac + 1][ar + i*64] = pa[i].y;
            As[ac + 2][ar + i*64] = pa[i].z; As[ac + 3][ar + i*64] = pa[i].w;
            Bs[ac + 0][ar + i*64] = pb[i].x; Bs[ac + 1][ar + i*64] = pb[i].y;
            Bs[ac + 2][ar + i*64] = pb[i].z; Bs[ac + 3][ar + i*64] = pb[i].w;
        }
        __syncthreads();

        int kn = k0 + 16;
        bool more = (kn < 64);
        if (more) {
            #pragma unroll
            for (int i = 0; i < 2; i++) {
                pa[i] = *(const float4*)&A [(size_t)(m0 + ar + i*64) * 64 + kn + ac];
                pb[i] = *(const float4*)&Bm[(size_t)(n0 + ar + i*64) * 64 + kn + ac];
            }
        }

        #pragma unroll
        for (int k = 0; k < 16; k++) {
            float4 a0 = *(const float4*)&As[k][tm * 8];
            float4 a1 = *(const float4*)&As[k][tm * 8 + 4];
            float4 b0 = *(const float4*)&Bs[k][tn * 8];
            float4 b1 = *(const float4*)&Bs[k][tn * 8 + 4];
            float av[8] = {a0.x, a0.y, a0.z, a0.w, a1.x, a1.y, a1.z, a1.w};
            float bv[8] = {b0.x, b0.y, b0.z, b0.w, b1.x, b1.y, b1.z, b1.w};
            #pragma unroll
            for (int i = 0; i < 8; i++)
                #pragma unroll
                for (int j = 0; j < 8; j++)
                    acc[i][j] += av[i] * bv[j];
        }
        if (!more) break;
        __syncthreads();
        k0 = kn;
    }

    #pragma unroll
    for (int i = 0; i < 8; i++)
        #pragma unroll
        for (int j = 0; j < 8; j++)
            C[(size_t)(m0 + tm*8 + i) * 2048 + n0 + tn*8 + j] = acc[i][j] * SCALE_;
}

// ---------------- mask + softmax (in-place on g_P) + mean over heads ----------------
// Block = (q, b), 256 threads; warp h owns row (b,h,q). Rows staged in smem so the
// head-sum for the mean runs in a fixed order (deterministic).
#define SMX_BYTES ((2048 + 8*2048) * 4)

__global__ __launch_bounds__(256)
void softmax_mean_k(const float* __restrict__ mask, float* __restrict__ mean_out)
{
    extern __shared__ float sm[];
    float* mrow = sm;            // [2048]
    float* p8   = sm + 2048;     // [8][2048]

    const int t = threadIdx.x, w = t >> 5, l = t & 31;
    const int q = blockIdx.x, b = blockIdx.y;

    const float4* maskv = (const float4*)(mask + (size_t)q * 2048);
    for (int i = t; i < 512; i += 256) ((float4*)mrow)[i] = maskv[i];
    __syncthreads();

    float* row = g_P + ((size_t)(b * 8 + w) * 2048 + q) * 2048;
    float4* rowv  = (float4*)row;
    float4* prow  = (float4*)(p8 + w * 2048);
    const float4* mv = (const float4*)mrow;

    float mx = -1e30f;
    for (int j = l; j < 512; j += 32) {
        float4 v = rowv[j], m = mv[j];
        mx = fmaxf(mx, fmaxf(fmaxf(v.x + m.x, v.y + m.y), fmaxf(v.z + m.z, v.w + m.w)));
    }
    #pragma unroll
    for (int o = 16; o > 0; o >>= 1) mx = fmaxf(mx, __shfl_xor_sync(0xffffffffu, mx, o));

    float sum = 0.f;
    for (int j = l; j < 512; j += 32) {
        float4 v = rowv[j], m = mv[j], e;
        e.x = __expf(v.x + m.x - mx); e.y = __expf(v.y + m.y - mx);
        e.z = __expf(v.z + m.z - mx); e.w = __expf(v.w + m.w - mx);
        sum += (e.x + e.y) + (e.z + e.w);
        prow[j] = e;
    }
    #pragma unroll
    for (int o = 16; o > 0; o >>= 1) sum += __shfl_xor_sync(0xffffffffu, sum, o);
    float inv = 1.f / sum;

    for (int j = l; j < 512; j += 32) {
        float4 e = prow[j];
        e.x *= inv; e.y *= inv; e.z *= inv; e.w *= inv;
        rowv[j] = e; prow[j] = e;
    }
    __syncthreads();

    float4* mo = (float4*)(mean_out + (size_t)(b * 2048 + q) * 2048);
    for (int j = t; j < 512; j += 256) {
        float4 s = {0.f, 0.f, 0.f, 0.f};
        #pragma unroll
        for (int h = 0; h < 8; h++) {
            float4 p = ((float4*)(p8 + h * 2048))[j];
            s.x += p.x; s.y += p.y; s.z += p.z; s.w += p.w;
        }
        s.x *= 0.125f; s.y *= 0.125f; s.z *= 0.125f; s.w *= 0.125f;
        mo[j] = s;
    }
}

// ---------------- launch ----------------
extern "C" void kernel_launch(void* const* d_in, const int* in_sizes, int n_in,
                              void* d_out, int out_size)
{
    const float* Zq   = (const float*)d_in[0];
    const float* Zkv  = (const float*)d_in[1];
    const float* mask = (const float*)d_in[2];
    const float* Wqkv = (const float*)d_in[3];
    const float* Wout = (const float*)d_in[4];
    float* out   = (float*)d_out;
    float* meanp = out + (size_t)B_ * S_ * D_;

    float *Qp, *Kp, *Vp, *Cp, *Pp;
    cudaGetSymbolAddress((void**)&Qp, g_Q);
    cudaGetSymbolAddress((void**)&Kp, g_K);
    cudaGetSymbolAddress((void**)&Vp, g_V);
    cudaGetSymbolAddress((void**)&Cp, g_ctx);
    cudaGetSymbolAddress((void**)&Pp, g_P);

    cudaFuncSetAttribute(softmax_mean_k,
                         cudaFuncAttributeMaxDynamicSharedMemorySize, SMX_BYTES);

    const int M = B_ * S_;   // 8192

    // Q projection: Zq @ Wq  (headsplit)
    gemm_nn<128, 1><<<dim3(4, M / 128), 256>>>(
        Zq, Wqkv, Qp, nullptr, M, 512, 512, 512, 3 * D_, 0);

    // K|V projection: Zkv @ [Wk|Wv]  (headsplit, dual dst)
    gemm_nn<128, 2><<<dim3(8, M / 128), 256>>>(
        Zkv, Wqkv + D_, Kp, Vp, M, 1024, 512, 512, 3 * D_, 0);

    // scores: P = Q @ K^T * scale  (batched over 32 bh)
    gemm_nt_scores<<<dim3(16, 16, 32), 256>>>(Qp, Kp, Pp);

    // mask + softmax (in place) + mean over heads
    softmax_mean_k<<<dim3(S_, B_), 256, SMX_BYTES>>>(mask, meanp);

    // ctx = P @ V  (batched over 32 bh, stores into [b][s][h*64+dk])
    gemm_nn<64, 3><<<dim3(1, 16, 32), 256>>>(
        Pp, Vp, Cp, nullptr, 2048, 64, 2048, 2048, 64, 512);

    // out = ctx @ Wout
    gemm_nn<128, 0><<<dim3(4, M / 128), 256>>>(
        Cp, Wout, out, nullptr, M, 512, 512, 512, 512, 512);
}

// round 9
// speedup vs baseline: 4.3794x; 1.4515x over previous
#include <cuda_runtime.h>
#include <cuda_bf16.h>
#include <cstdint>

#define B_   4
#define S_   2048
#define D_   512
#define H_   8
#define DK_  64
#define SCALE_ 0.125f

#define NQK ((size_t)B_*H_*S_*DK_)
#define NSS ((size_t)B_*H_*S_*S_)

// ---------------- scratch ----------------
__device__ __nv_bfloat16 g_Qh[NQK], g_Qm[NQK], g_Ql[NQK];
__device__ __nv_bfloat16 g_Kh[NQK], g_Km[NQK], g_Kl[NQK];
__device__ __nv_bfloat16 g_Vth[NQK], g_Vtl[NQK];      // transposed [bh][dk][s]
__device__ float         g_S[NSS];                     // raw scores * SCALE
__device__ __nv_bfloat16 g_Ph[NSS], g_Pl[NSS];         // prob splits
__device__ float         g_ctx[(size_t)B_*S_*D_];

// ---------------- helpers ----------------
__device__ __forceinline__ uint32_t smem_u32(const void* p){
    uint32_t a; asm("{ .reg .u64 t; cvta.to.shared.u64 t,%1; cvt.u32.u64 %0,t; }":"=r"(a):"l"(p)); return a;
}
#define LDSM_X4(r0,r1,r2,r3,addr) \
    asm volatile("ldmatrix.sync.aligned.m8n8.x4.shared.b16 {%0,%1,%2,%3},[%4];" \
        :"=r"(r0),"=r"(r1),"=r"(r2),"=r"(r3):"r"(addr))
#define MMA16816(d,a,b) \
    asm volatile("mma.sync.aligned.m16n8k16.row.col.f32.bf16.bf16.f32 " \
        "{%0,%1,%2,%3},{%4,%5,%6,%7},{%8,%9},{%0,%1,%2,%3};" \
        : "+f"((d)[0]),"+f"((d)[1]),"+f"((d)[2]),"+f"((d)[3]) \
        : "r"((a)[0]),"r"((a)[1]),"r"((a)[2]),"r"((a)[3]),"r"((b)[0]),"r"((b)[1]))

__device__ __forceinline__ void split3(float v, __nv_bfloat16& h, __nv_bfloat16& m, __nv_bfloat16& l){
    h = __float2bfloat16_rn(v); float r  = v - __bfloat162float(h);
    m = __float2bfloat16_rn(r); float r2 = r - __bfloat162float(m);
    l = __float2bfloat16_rn(r2);
}

// ---------------- fp32 pipelined GEMM (NN) ----------------
// MODE 0: plain store. MODE 1: Q proj -> 3-way bf16 splits.
// MODE 2: KV proj -> K 3-way splits (gn<512), V transposed 2-way splits (gn>=512).
template<int MODE>
__global__ __launch_bounds__(256)
void gemm_nn(const float* __restrict__ A, const float* __restrict__ Bw,
             float* __restrict__ C, int M, int K, int lda, int ldb, int ldc)
{
    __shared__ float As[16][132];
    __shared__ float Bs[16][128];
    const int t  = threadIdx.x;
    const int m0 = blockIdx.y * 128;
    const int n0 = blockIdx.x * 128;
    const int tm = t >> 4, tn = t & 15;
    const int ar = t >> 2, ac = (t & 3) << 2;
    const int br = t >> 5, bc = (t & 31) << 2;

    float4 pa[2], pb[2];
    #pragma unroll
    for (int i = 0; i < 2; i++)
        pa[i] = *(const float4*)&A[(size_t)(m0 + ar + i*64) * lda + ac];
    #pragma unroll
    for (int i = 0; i < 2; i++)
        pb[i] = *(const float4*)&Bw[(size_t)(br + i*8) * ldb + n0 + bc];

    float acc[8][8];
    #pragma unroll
    for (int i = 0; i < 8; i++)
        #pragma unroll
        for (int j = 0; j < 8; j++) acc[i][j] = 0.f;

    int k0 = 0;
    while (true) {
        #pragma unroll
        for (int i = 0; i < 2; i++) {
            As[ac+0][ar+i*64] = pa[i].x; As[ac+1][ar+i*64] = pa[i].y;
            As[ac+2][ar+i*64] = pa[i].z; As[ac+3][ar+i*64] = pa[i].w;
        }
        #pragma unroll
        for (int i = 0; i < 2; i++)
            *(float4*)&Bs[br + i*8][bc] = pb[i];
        __syncthreads();

        int kn = k0 + 16;
        bool more = (kn < K);
        if (more) {
            #pragma unroll
            for (int i = 0; i < 2; i++)
                pa[i] = *(const float4*)&A[(size_t)(m0 + ar + i*64) * lda + kn + ac];
            #pragma unroll
            for (int i = 0; i < 2; i++)
                pb[i] = *(const float4*)&Bw[(size_t)(kn + br + i*8) * ldb + n0 + bc];
        }
        #pragma unroll
        for (int k = 0; k < 16; k++) {
            float4 a0 = *(const float4*)&As[k][tm*8];
            float4 a1 = *(const float4*)&As[k][tm*8+4];
            float4 b0 = *(const float4*)&Bs[k][tn*8];
            float4 b1 = *(const float4*)&Bs[k][tn*8+4];
            float av[8] = {a0.x,a0.y,a0.z,a0.w,a1.x,a1.y,a1.z,a1.w};
            float bv[8] = {b0.x,b0.y,b0.z,b0.w,b1.x,b1.y,b1.z,b1.w};
            #pragma unroll
            for (int i = 0; i < 8; i++)
                #pragma unroll
                for (int j = 0; j < 8; j++)
                    acc[i][j] += av[i] * bv[j];
        }
        if (!more) break;
        __syncthreads();
        k0 = kn;
    }

    #pragma unroll
    for (int i = 0; i < 8; i++) {
        int gm = m0 + tm*8 + i;
        int b = gm >> 11, s = gm & 2047;
        #pragma unroll
        for (int j = 0; j < 8; j++) {
            int gn = n0 + tn*8 + j;
            float v = acc[i][j];
            if (MODE == 0) {
                C[(size_t)gm * ldc + gn] = v;
            } else if (MODE == 1) {
                int hh = gn >> 6, dk = gn & 63;
                size_t qi = ((size_t)((b<<3)+hh)*2048 + s)*64 + dk;
                __nv_bfloat16 x,y,z; split3(v,x,y,z);
                g_Qh[qi]=x; g_Qm[qi]=y; g_Ql[qi]=z;
            } else { // MODE 2
                if (gn < 512) {
                    int hh = gn >> 6, dk = gn & 63;
                    size_t ki = ((size_t)((b<<3)+hh)*2048 + s)*64 + dk;
                    __nv_bfloat16 x,y,z; split3(v,x,y,z);
                    g_Kh[ki]=x; g_Km[ki]=y; g_Kl[ki]=z;
                } else {
                    int gn2 = gn - 512;
                    int hh = gn2 >> 6, dk = gn2 & 63;
                    __nv_bfloat16 vh = __float2bfloat16_rn(v);
                    __nv_bfloat16 vl = __float2bfloat16_rn(v - __bfloat162float(vh));
                    size_t vi = ((size_t)((b<<3)+hh)*64 + dk)*2048 + s;
                    g_Vth[vi]=vh; g_Vtl[vi]=vl;
                }
            }
        }
    }
}

// ---------------- HMMA scores: S = (Qh+Qm+Ql)(Kh+Km+Kl)^T * SCALE ----------------
// CTA: 128x128 tile per bh. 256 thr = 8 warps (2x4), warp tile 64x32.
// smem: 6 tiles [128][72] bf16 (pad 72 -> conflict-free ldmatrix).
#define SC_PAD   72
#define SC_TILE  (128 * SC_PAD)
#define SC_SMEM  (6 * SC_TILE * 2)
__global__ __launch_bounds__(256)
void scores_mma()
{
    extern __shared__ __nv_bfloat16 smt[];
    const int t = threadIdx.x, lane = t & 31, wid = t >> 5;
    const int bh = blockIdx.z, m0 = blockIdx.y * 128, n0 = blockIdx.x * 128;

    // load 6 tiles
    {
        const size_t qoff = ((size_t)bh*2048 + m0)*64;
        const size_t koff = ((size_t)bh*2048 + n0)*64;
        const __nv_bfloat16* gsrc[6] = { g_Qh+qoff, g_Qm+qoff, g_Ql+qoff,
                                         g_Kh+koff, g_Km+koff, g_Kl+koff };
        #pragma unroll
        for (int tl = 0; tl < 6; tl++) {
            const uint4* src = (const uint4*)gsrc[tl];
            uint4* dst = (uint4*)(smt + tl*SC_TILE);
            #pragma unroll
            for (int it = 0; it < 4; it++) {
                int idx = t + it*256;
                int r = idx >> 3, cc = idx & 7;
                dst[r*9 + cc] = src[r*8 + cc];
            }
        }
    }
    __syncthreads();

    const int wm = (wid & 1) * 64, wn = (wid >> 1) * 32;
    const int arw = lane & 15, acg = (lane >> 4) * 8;                 // A frag addr
    const int brw = ((lane >> 4) << 3) + (lane & 7), bcg = ((lane >> 3) & 1) * 8; // B frag addr

    float acc[4][4][4];
    #pragma unroll
    for (int i=0;i<4;i++) for (int j=0;j<4;j++) for (int k=0;k<4;k++) acc[i][j][k]=0.f;

    const int pq[6] = {0,0,1,1,0,2};
    const int pk[6] = {0,1,0,1,2,0};
    const uint32_t smb = smem_u32(smt);

    for (int p = 0; p < 6; p++) {
        const uint32_t QT = smb + pq[p]*SC_TILE*2;
        const uint32_t KT = smb + (3+pk[p])*SC_TILE*2;
        #pragma unroll
        for (int ks = 0; ks < 4; ks++) {
            uint32_t a[4][4], bfr[4][2];
            #pragma unroll
            for (int mi = 0; mi < 4; mi++) {
                uint32_t addr = QT + ((wm + mi*16 + arw)*SC_PAD + ks*16 + acg)*2;
                LDSM_X4(a[mi][0], a[mi][1], a[mi][2], a[mi][3], addr);
            }
            #pragma unroll
            for (int ng = 0; ng < 2; ng++) {
                uint32_t addr = KT + ((wn + ng*16 + brw)*SC_PAD + ks*16 + bcg)*2;
                uint32_t b0,b1,b2,b3;
                LDSM_X4(b0, b1, b2, b3, addr);
                bfr[ng*2][0]=b0; bfr[ng*2][1]=b1; bfr[ng*2+1][0]=b2; bfr[ng*2+1][1]=b3;
            }
            #pragma unroll
            for (int mi = 0; mi < 4; mi++)
                #pragma unroll
                for (int ni = 0; ni < 4; ni++)
                    MMA16816(acc[mi][ni], a[mi], bfr[ni]);
        }
    }

    float* Crow = g_S + (size_t)bh*2048*2048;
    #pragma unroll
    for (int mi = 0; mi < 4; mi++) {
        #pragma unroll
        for (int ni = 0; ni < 4; ni++) {
            int row = m0 + wm + mi*16 + (lane >> 2);
            int col = n0 + wn + ni*8 + (lane & 3)*2;
            float2 v0 = { acc[mi][ni][0]*SCALE_, acc[mi][ni][1]*SCALE_ };
            float2 v1 = { acc[mi][ni][2]*SCALE_, acc[mi][ni][3]*SCALE_ };
            *(float2*)&Crow[(size_t)row*2048 + col]     = v0;
            *(float2*)&Crow[(size_t)(row+8)*2048 + col] = v1;
        }
    }
}

// ---------------- softmax + mean + bf16 split of P ----------------
#define SMX_BYTES ((2048 + 8*2048) * 4)
__global__ __launch_bounds__(256)
void softmax_mean_k(const float* __restrict__ mask, float* __restrict__ mean_out)
{
    extern __shared__ float smf[];
    float* mrow = smf;
    float* p8   = smf + 2048;

    const int t = threadIdx.x, w = t >> 5, l = t & 31;
    const int q = blockIdx.x, b = blockIdx.y;

    const float4* maskv = (const float4*)(mask + (size_t)q * 2048);
    for (int i = t; i < 512; i += 256) ((float4*)mrow)[i] = maskv[i];
    __syncthreads();

    const size_t rbase = ((size_t)(b*8 + w)*2048 + q)*2048;
    const float4* rowv = (const float4*)(g_S + rbase);
    float4* prow = (float4*)(p8 + w*2048);
    const float4* mv = (const float4*)mrow;

    float mx = -1e30f;
    for (int j = l; j < 512; j += 32) {
        float4 v = rowv[j], m = mv[j];
        mx = fmaxf(mx, fmaxf(fmaxf(v.x+m.x, v.y+m.y), fmaxf(v.z+m.z, v.w+m.w)));
    }
    #pragma unroll
    for (int o = 16; o > 0; o >>= 1) mx = fmaxf(mx, __shfl_xor_sync(0xffffffffu, mx, o));

    float sum = 0.f;
    for (int j = l; j < 512; j += 32) {
        float4 v = rowv[j], m = mv[j], e;
        e.x = __expf(v.x+m.x-mx); e.y = __expf(v.y+m.y-mx);
        e.z = __expf(v.z+m.z-mx); e.w = __expf(v.w+m.w-mx);
        sum += (e.x+e.y)+(e.z+e.w);
        prow[j] = e;
    }
    #pragma unroll
    for (int o = 16; o > 0; o >>= 1) sum += __shfl_xor_sync(0xffffffffu, sum, o);
    const float inv = 1.f / sum;

    __nv_bfloat162* phv = (__nv_bfloat162*)(g_Ph + rbase);
    __nv_bfloat162* plv = (__nv_bfloat162*)(g_Pl + rbase);
    for (int j = l; j < 512; j += 32) {
        float4 e = prow[j];
        e.x *= inv; e.y *= inv; e.z *= inv; e.w *= inv;
        prow[j] = e;
        __nv_bfloat16 h0=__float2bfloat16_rn(e.x), h1=__float2bfloat16_rn(e.y);
        __nv_bfloat16 h2=__float2bfloat16_rn(e.z), h3=__float2bfloat16_rn(e.w);
        phv[2*j]   = __nv_bfloat162(h0, h1);
        phv[2*j+1] = __nv_bfloat162(h2, h3);
        plv[2*j]   = __nv_bfloat162(__float2bfloat16_rn(e.x-__bfloat162float(h0)),
                                    __float2bfloat16_rn(e.y-__bfloat162float(h1)));
        plv[2*j+1] = __nv_bfloat162(__float2bfloat16_rn(e.z-__bfloat162float(h2)),
                                    __float2bfloat16_rn(e.w-__bfloat162float(h3)));
    }
    __syncthreads();

    float4* mo = (float4*)(mean_out + (size_t)(b*2048 + q)*2048);
    for (int j = t; j < 512; j += 256) {
        float4 s = {0.f,0.f,0.f,0.f};
        #pragma unroll
        for (int h = 0; h < 8; h++) {
            float4 p = ((float4*)(p8 + h*2048))[j];
            s.x += p.x; s.y += p.y; s.z += p.z; s.w += p.w;
        }
        s.x *= 0.125f; s.y *= 0.125f; s.z *= 0.125f; s.w *= 0.125f;
        mo[j] = s;
    }
}

// ---------------- HMMA PV: ctx = (Ph+Pl) @ (Vth+Vtl)^T ----------------
// CTA: 128x64 tile per bh, K=2048 in chunks of 64. 256 thr = 8 warps (4x2),
// warp tile 32x32. Reg-prefetch single smem buffer.
#define PV_PAD  72
#define PV_PT   (128 * PV_PAD)
#define PV_VT   (64 * PV_PAD)
#define PV_SMEM ((2*PV_PT + 2*PV_VT) * 2)
__global__ __launch_bounds__(256)
void pv_mma()
{
    extern __shared__ __nv_bfloat16 smp[];
    __nv_bfloat16* PhT = smp;
    __nv_bfloat16* PlT = smp + PV_PT;
    __nv_bfloat16* VhT = smp + 2*PV_PT;
    __nv_bfloat16* VlT = VhT + PV_VT;

    const int t = threadIdx.x, lane = t & 31, wid = t >> 5;
    const int bh = blockIdx.z, b = bh >> 3, h = bh & 7;
    const int m0 = blockIdx.x * 128;

    const uint4* PhG = (const uint4*)(g_Ph  + ((size_t)bh*2048 + m0)*2048);
    const uint4* PlG = (const uint4*)(g_Pl  + ((size_t)bh*2048 + m0)*2048);
    const uint4* VhG = (const uint4*)(g_Vth + (size_t)bh*64*2048);
    const uint4* VlG = (const uint4*)(g_Vtl + (size_t)bh*64*2048);

    const int wm = (wid & 3) * 32, wn = (wid >> 2) * 32;
    const int arw = lane & 15, acg = (lane >> 4) * 8;
    const int brw = ((lane >> 4) << 3) + (lane & 7), bcg = ((lane >> 3) & 1) * 8;
    const uint32_t smb = smem_u32(smp);

    float acc[2][4][4];
    #pragma unroll
    for (int i=0;i<2;i++) for (int j=0;j<4;j++) for (int k=0;k<4;k++) acc[i][j][k]=0.f;

    const int pr = t >> 3, pc = t & 7;          // P load: 4 iters of (r, cc)
    const int vr = (t & 127) >> 3;              // V load: lower half threads rows 0-31? no:
    // V: 512 uint4 / 256 thr = 2 iters: idx = t + it*256 -> r = idx>>3 (0..63), cc = idx&7

    uint4 rp[4], rl[4], rvh[2], rvl[2];
    // prefetch chunk 0
    #pragma unroll
    for (int it = 0; it < 4; it++) {
        int r = pr + it*32;
        rp[it] = PhG[(size_t)r*256 + pc];
        rl[it] = PlG[(size_t)r*256 + pc];
    }
    #pragma unroll
    for (int it = 0; it < 2; it++) {
        int idx = t + it*256, r = idx >> 3, cc = idx & 7;
        rvh[it] = VhG[(size_t)r*256 + cc];
        rvl[it] = VlG[(size_t)r*256 + cc];
    }

    for (int c = 0; c < 32; c++) {
        // store prefetched chunk
        #pragma unroll
        for (int it = 0; it < 4; it++) {
            int r = pr + it*32;
            ((uint4*)PhT)[r*9 + pc] = rp[it];
            ((uint4*)PlT)[r*9 + pc] = rl[it];
        }
        #pragma unroll
        for (int it = 0; it < 2; it++) {
            int idx = t + it*256, r = idx >> 3, cc = idx & 7;
            ((uint4*)VhT)[r*9 + cc] = rvh[it];
            ((uint4*)VlT)[r*9 + cc] = rvl[it];
        }
        __syncthreads();

        if (c < 31) {
            const int kq = (c+1) * 8;
            #pragma unroll
            for (int it = 0; it < 4; it++) {
                int r = pr + it*32;
                rp[it] = PhG[(size_t)r*256 + kq + pc];
                rl[it] = PlG[(size_t)r*256 + kq + pc];
            }
            #pragma unroll
            for (int it = 0; it < 2; it++) {
                int idx = t + it*256, r = idx >> 3, cc = idx & 7;
                rvh[it] = VhG[(size_t)r*256 + kq + cc];
                rvl[it] = VlG[(size_t)r*256 + kq + cc];
            }
        }

        const uint32_t PT2[2] = { smb,               smb + PV_PT*2 };
        const uint32_t VT2[2] = { smb + 2*PV_PT*2,   smb + 2*PV_PT*2 + PV_VT*2 };
        const int tp[3] = {0, 0, 1};   // Ph,Ph,Pl
        const int tv[3] = {0, 1, 0};   // Vh,Vl,Vh
        #pragma unroll
        for (int p = 0; p < 3; p++) {
            const uint32_t PT = PT2[tp[p]], VT = VT2[tv[p]];
            #pragma unroll
            for (int ks = 0; ks < 4; ks++) {
                uint32_t a[2][4], bfr[4][2];
                #pragma unroll
                for (int mi = 0; mi < 2; mi++) {
                    uint32_t addr = PT + ((wm + mi*16 + arw)*PV_PAD + ks*16 + acg)*2;
                    LDSM_X4(a[mi][0], a[mi][1], a[mi][2], a[mi][3], addr);
                }
                #pragma unroll
                for (int ng = 0; ng < 2; ng++) {
                    uint32_t addr = VT + ((wn + ng*16 + brw)*PV_PAD + ks*16 + bcg)*2;
                    uint32_t b0,b1,b2,b3;
                    LDSM_X4(b0, b1, b2, b3, addr);
                    bfr[ng*2][0]=b0; bfr[ng*2][1]=b1; bfr[ng*2+1][0]=b2; bfr[ng*2+1][1]=b3;
                }
                #pragma unroll
                for (int mi = 0; mi < 2; mi++)
                    #pragma unroll
                    for (int ni = 0; ni < 4; ni++)
                        MMA16816(acc[mi][ni], a[mi], bfr[ni]);
            }
        }
        __syncthreads();
    }

    float* dst = g_ctx + ((size_t)(b*2048 + m0))*512 + h*64;
    #pragma unroll
    for (int mi = 0; mi < 2; mi++) {
        #pragma unroll
        for (int ni = 0; ni < 4; ni++) {
            int row = wm + mi*16 + (lane >> 2);
            int col = wn + ni*8 + (lane & 3)*2;
            float2 v0 = { acc[mi][ni][0], acc[mi][ni][1] };
            float2 v1 = { acc[mi][ni][2], acc[mi][ni][3] };
            *(float2*)&dst[(size_t)row*512 + col]     = v0;
            *(float2*)&dst[(size_t)(row+8)*512 + col] = v1;
        }
    }
}

// ---------------- launch ----------------
extern "C" void kernel_launch(void* const* d_in, const int* in_sizes, int n_in,
                              void* d_out, int out_size)
{
    const float* Zq   = (const float*)d_in[0];
    const float* Zkv  = (const float*)d_in[1];
    const float* mask = (const float*)d_in[2];
    const float* Wqkv = (const float*)d_in[3];
    const float* Wout = (const float*)d_in[4];
    float* out   = (float*)d_out;
    float* meanp = out + (size_t)B_ * S_ * D_;

    float* Cp;
    cudaGetSymbolAddress((void**)&Cp, g_ctx);

    cudaFuncSetAttribute(softmax_mean_k, cudaFuncAttributeMaxDynamicSharedMemorySize, SMX_BYTES);
    cudaFuncSetAttribute(scores_mma,     cudaFuncAttributeMaxDynamicSharedMemorySize, SC_SMEM);
    cudaFuncSetAttribute(pv_mma,         cudaFuncAttributeMaxDynamicSharedMemorySize, PV_SMEM);

    const int M = B_ * S_;   // 8192

    // Q projection -> 3-way bf16 splits
    gemm_nn<1><<<dim3(4, M/128), 256>>>(Zq, Wqkv, nullptr, M, 512, 512, 3*D_, 0);

    // K|V projection -> K 3-way splits, V transposed 2-way splits
    gemm_nn<2><<<dim3(8, M/128), 256>>>(Zkv, Wqkv + D_, nullptr, M, 512, 512, 3*D_, 0);

    // scores via HMMA (6-term bf16 split ~= fp32)
    scores_mma<<<dim3(16, 16, 32), 256, SC_SMEM>>>();

    // softmax + mean + P bf16 split
    softmax_mean_k<<<dim3(S_, B_), 256, SMX_BYTES>>>(mask, meanp);

    // ctx = P @ V via HMMA (3-term bf16 split)
    pv_mma<<<dim3(16, 1, 32), 256, PV_SMEM>>>();

    // out = ctx @ Wout (fp32)
    gemm_nn<0><<<dim3(4, M/128), 256>>>(Cp, Wout, out, M, 512, 512, 512, 512);
}

// round 12
// speedup vs baseline: 4.5535x; 1.0398x over previous
#include <cuda_runtime.h>
#include <cuda_bf16.h>
#include <cstdint>

#define B_   4
#define S_   2048
#define D_   512
#define H_   8
#define DK_  64
#define SCALE_ 0.125f

#define NQK ((size_t)B_*H_*S_*DK_)
#define NSS ((size_t)B_*H_*S_*S_)

// ---------------- scratch ----------------
__device__ __nv_bfloat16 g_Qh[NQK], g_Qm[NQK], g_Ql[NQK];
__device__ __nv_bfloat16 g_Kh[NQK], g_Km[NQK], g_Kl[NQK];
__device__ __nv_bfloat16 g_Vth[NQK], g_Vtl[NQK];      // transposed [bh][dk][s]
__device__ float         g_S[NSS];                     // raw scores * SCALE
__device__ __nv_bfloat16 g_Ph[NSS], g_Pl[NSS];         // prob splits
__device__ float         g_ctx[(size_t)B_*S_*D_];

// ---------------- helpers ----------------
__device__ __forceinline__ uint32_t smem_u32(const void* p){
    uint32_t a; asm("{ .reg .u64 t; cvta.to.shared.u64 t,%1; cvt.u32.u64 %0,t; }":"=r"(a):"l"(p)); return a;
}
#define LDSM_X4(r0,r1,r2,r3,addr) \
    asm volatile("ldmatrix.sync.aligned.m8n8.x4.shared.b16 {%0,%1,%2,%3},[%4];" \
        :"=r"(r0),"=r"(r1),"=r"(r2),"=r"(r3):"r"(addr))
#define MMA16816(d,a,b) \
    asm volatile("mma.sync.aligned.m16n8k16.row.col.f32.bf16.bf16.f32 " \
        "{%0,%1,%2,%3},{%4,%5,%6,%7},{%8,%9},{%0,%1,%2,%3};" \
        : "+f"((d)[0]),"+f"((d)[1]),"+f"((d)[2]),"+f"((d)[3]) \
        : "r"((a)[0]),"r"((a)[1]),"r"((a)[2]),"r"((a)[3]),"r"((b)[0]),"r"((b)[1]))

__device__ __forceinline__ void split3(float v, __nv_bfloat16& h, __nv_bfloat16& m, __nv_bfloat16& l){
    h = __float2bfloat16_rn(v); float r  = v - __bfloat162float(h);
    m = __float2bfloat16_rn(r); float r2 = r - __bfloat162float(m);
    l = __float2bfloat16_rn(r2);
}

// ---------------- fp32 pipelined GEMM (NN) ----------------
// MODE 0: plain store. MODE 1: Q proj -> 3-way bf16 splits (packed stores).
// MODE 2: KV proj -> K 3-way splits (n0<512), V transposed 2-way splits (n0>=512).
template<int MODE>
__global__ __launch_bounds__(256)
void gemm_nn(const float* __restrict__ A, const float* __restrict__ Bw,
             float* __restrict__ C, int M, int K, int lda, int ldb, int ldc)
{
    __shared__ float As[16][132];
    __shared__ float Bs[16][128];
    const int t  = threadIdx.x;
    const int m0 = blockIdx.y * 128;
    const int n0 = blockIdx.x * 128;
    const int tm = t >> 4, tn = t & 15;
    const int ar = t >> 2, ac = (t & 3) << 2;
    const int br = t >> 5, bc = (t & 31) << 2;

    float4 pa[2], pb[2];
    #pragma unroll
    for (int i = 0; i < 2; i++)
        pa[i] = *(const float4*)&A[(size_t)(m0 + ar + i*64) * lda + ac];
    #pragma unroll
    for (int i = 0; i < 2; i++)
        pb[i] = *(const float4*)&Bw[(size_t)(br + i*8) * ldb + n0 + bc];

    float acc[8][8];
    #pragma unroll
    for (int i = 0; i < 8; i++)
        #pragma unroll
        for (int j = 0; j < 8; j++) acc[i][j] = 0.f;

    int k0 = 0;
    while (true) {
        #pragma unroll
        for (int i = 0; i < 2; i++) {
            As[ac+0][ar+i*64] = pa[i].x; As[ac+1][ar+i*64] = pa[i].y;
            As[ac+2][ar+i*64] = pa[i].z; As[ac+3][ar+i*64] = pa[i].w;
        }
        #pragma unroll
        for (int i = 0; i < 2; i++)
            *(float4*)&Bs[br + i*8][bc] = pb[i];
        __syncthreads();

        int kn = k0 + 16;
        bool more = (kn < K);
        if (more) {
            #pragma unroll
            for (int i = 0; i < 2; i++)
                pa[i] = *(const float4*)&A[(size_t)(m0 + ar + i*64) * lda + kn + ac];
            #pragma unroll
            for (int i = 0; i < 2; i++)
                pb[i] = *(const float4*)&Bw[(size_t)(kn + br + i*8) * ldb + n0 + bc];
        }
        #pragma unroll
        for (int k = 0; k < 16; k++) {
            float4 a0 = *(const float4*)&As[k][tm*8];
            float4 a1 = *(const float4*)&As[k][tm*8+4];
            float4 b0 = *(const float4*)&Bs[k][tn*8];
            float4 b1 = *(const float4*)&Bs[k][tn*8+4];
            float av[8] = {a0.x,a0.y,a0.z,a0.w,a1.x,a1.y,a1.z,a1.w};
            float bv[8] = {b0.x,b0.y,b0.z,b0.w,b1.x,b1.y,b1.z,b1.w};
            #pragma unroll
            for (int i = 0; i < 8; i++)
                #pragma unroll
                for (int j = 0; j < 8; j++)
                    acc[i][j] += av[i] * bv[j];
        }
        if (!more) break;
        __syncthreads();
        k0 = kn;
    }

    const int bb = m0 >> 11;            // batch constant over CTA tile
    const int s0 = (m0 & 2047) + tm*8;  // 8 consecutive s rows for this thread

    if (MODE == 0) {
        #pragma unroll
        for (int i = 0; i < 8; i++) {
            int gm = m0 + tm*8 + i;
            #pragma unroll
            for (int j = 0; j < 8; j++)
                C[(size_t)gm * ldc + n0 + tn*8 + j] = acc[i][j];
        }
    } else if (MODE == 1 || (MODE == 2 && n0 < 512)) {
        // Q or K: 3-way split, packed 16B stores along dk
        const int gn0 = n0 + tn*8;
        const int hh = gn0 >> 6, dk = gn0 & 63;
        __nv_bfloat16* d0 = (MODE == 1) ? g_Qh : g_Kh;
        __nv_bfloat16* d1 = (MODE == 1) ? g_Qm : g_Km;
        __nv_bfloat16* d2 = (MODE == 1) ? g_Ql : g_Kl;
        #pragma unroll
        for (int i = 0; i < 8; i++) {
            size_t qi = ((size_t)((bb<<3)+hh)*2048 + s0 + i)*64 + dk;
            __align__(16) __nv_bfloat16 xh[8], xm[8], xl[8];
            #pragma unroll
            for (int j = 0; j < 8; j++) split3(acc[i][j], xh[j], xm[j], xl[j]);
            *(uint4*)&d0[qi] = *(uint4*)xh;
            *(uint4*)&d1[qi] = *(uint4*)xm;
            *(uint4*)&d2[qi] = *(uint4*)xl;
        }
    } else {
        // V: 2-way split, transposed layout; pack 8 consecutive s per dk column
        const int gn0 = n0 - 512 + tn*8;
        const int hh = gn0 >> 6, dk0 = gn0 & 63;
        #pragma unroll
        for (int j = 0; j < 8; j++) {
            __align__(16) __nv_bfloat16 vh[8], vl[8];
            #pragma unroll
            for (int i = 0; i < 8; i++) {
                float v = acc[i][j];
                vh[i] = __float2bfloat16_rn(v);
                vl[i] = __float2bfloat16_rn(v - __bfloat162float(vh[i]));
            }
            size_t vi = ((size_t)((bb<<3)+hh)*64 + dk0 + j)*2048 + s0;
            *(uint4*)&g_Vth[vi] = *(uint4*)vh;
            *(uint4*)&g_Vtl[vi] = *(uint4*)vl;
        }
    }
}

// ---------------- HMMA scores: S = (Qh+Qm+Ql)(Kh+Km+Kl)^T * SCALE ----------------
#define SC_PAD   72
#define SC_TILE  (128 * SC_PAD)
#define SC_SMEM  (6 * SC_TILE * 2)
__global__ __launch_bounds__(256)
void scores_mma()
{
    extern __shared__ __nv_bfloat16 smt[];
    const int t = threadIdx.x, lane = t & 31, wid = t >> 5;
    const int bh = blockIdx.z, m0 = blockIdx.y * 128, n0 = blockIdx.x * 128;

    {
        const size_t qoff = ((size_t)bh*2048 + m0)*64;
        const size_t koff = ((size_t)bh*2048 + n0)*64;
        const __nv_bfloat16* gsrc[6] = { g_Qh+qoff, g_Qm+qoff, g_Ql+qoff,
                                         g_Kh+koff, g_Km+koff, g_Kl+koff };
        #pragma unroll
        for (int tl = 0; tl < 6; tl++) {
            const uint4* src = (const uint4*)gsrc[tl];
            uint4* dst = (uint4*)(smt + tl*SC_TILE);
            #pragma unroll
            for (int it = 0; it < 4; it++) {
                int idx = t + it*256;
                int r = idx >> 3, cc = idx & 7;
                dst[r*9 + cc] = src[r*8 + cc];
            }
        }
    }
    __syncthreads();

    const int wm = (wid & 1) * 64, wn = (wid >> 1) * 32;
    const int arw = lane & 15, acg = (lane >> 4) * 8;
    const int brw = ((lane >> 4) << 3) + (lane & 7), bcg = ((lane >> 3) & 1) * 8;

    float acc[4][4][4];
    #pragma unroll
    for (int i=0;i<4;i++) for (int j=0;j<4;j++) for (int k=0;k<4;k++) acc[i][j][k]=0.f;

    const int pq[6] = {0,0,1,1,0,2};
    const int pk[6] = {0,1,0,1,2,0};
    const uint32_t smb = smem_u32(smt);

    for (int p = 0; p < 6; p++) {
        const uint32_t QT = smb + pq[p]*SC_TILE*2;
        const uint32_t KT = smb + (3+pk[p])*SC_TILE*2;
        #pragma unroll
        for (int ks = 0; ks < 4; ks++) {
            uint32_t a[4][4], bfr[4][2];
            #pragma unroll
            for (int mi = 0; mi < 4; mi++) {
                uint32_t addr = QT + ((wm + mi*16 + arw)*SC_PAD + ks*16 + acg)*2;
                LDSM_X4(a[mi][0], a[mi][1], a[mi][2], a[mi][3], addr);
            }
            #pragma unroll
            for (int ng = 0; ng < 2; ng++) {
                uint32_t addr = KT + ((wn + ng*16 + brw)*SC_PAD + ks*16 + bcg)*2;
                uint32_t b0,b1,b2,b3;
                LDSM_X4(b0, b1, b2, b3, addr);
                bfr[ng*2][0]=b0; bfr[ng*2][1]=b1; bfr[ng*2+1][0]=b2; bfr[ng*2+1][1]=b3;
            }
            #pragma unroll
            for (int mi = 0; mi < 4; mi++)
                #pragma unroll
                for (int ni = 0; ni < 4; ni++)
                    MMA16816(acc[mi][ni], a[mi], bfr[ni]);
        }
    }

    float* Crow = g_S + (size_t)bh*2048*2048;
    #pragma unroll
    for (int mi = 0; mi < 4; mi++) {
        #pragma unroll
        for (int ni = 0; ni < 4; ni++) {
            int row = m0 + wm + mi*16 + (lane >> 2);
            int col = n0 + wn + ni*8 + (lane & 3)*2;
            float2 v0 = { acc[mi][ni][0]*SCALE_, acc[mi][ni][1]*SCALE_ };
            float2 v1 = { acc[mi][ni][2]*SCALE_, acc[mi][ni][3]*SCALE_ };
            *(float2*)&Crow[(size_t)row*2048 + col]     = v0;
            *(float2*)&Crow[(size_t)(row+8)*2048 + col] = v1;
        }
    }
}

// ---------------- two-pass online softmax + mean + bf16 split of P ----------------
// Block = (q, b), 256 threads, warp w = head w. 24KB static smem -> high occupancy.
// Pass 1: stream S row once, online (max,sum). Pass 2: re-read S (L2-hot), write
// Ph/Pl, accumulate head-mean through an 8x512 chunk buffer (deterministic order).
__global__ __launch_bounds__(256)
void softmax_mean_k(const float* __restrict__ mask, float* __restrict__ mean_out)
{
    __shared__ __align__(16) float mrow[2048];
    __shared__ __align__(16) float pbuf[8][512];

    const int t = threadIdx.x, w = t >> 5, l = t & 31;
    const int q = blockIdx.x, b = blockIdx.y;

    const float4* maskv = (const float4*)(mask + (size_t)q * 2048);
    for (int i = t; i < 512; i += 256) ((float4*)mrow)[i] = maskv[i];
    __syncthreads();

    const size_t rbase = ((size_t)(b*8 + w)*2048 + q)*2048;
    const float4* rowv = (const float4*)(g_S + rbase);
    const float4* mv = (const float4*)mrow;

    // ---- pass 1: online max + sum ----
    float m = -1e30f, s = 0.f;
    for (int j = l; j < 512; j += 32) {
        float4 v = rowv[j], mk = mv[j];
        float x0 = v.x+mk.x, x1 = v.y+mk.y, x2 = v.z+mk.z, x3 = v.w+mk.w;
        float lm = fmaxf(fmaxf(x0,x1), fmaxf(x2,x3));
        if (lm > m) { s *= __expf(m - lm); m = lm; }
        s += __expf(x0-m) + __expf(x1-m) + __expf(x2-m) + __expf(x3-m);
    }
    #pragma unroll
    for (int o = 16; o > 0; o >>= 1) {
        float mo = __shfl_xor_sync(0xffffffffu, m, o);
        float so = __shfl_xor_sync(0xffffffffu, s, o);
        float nm = fmaxf(m, mo);
        s = s*__expf(m-nm) + so*__expf(mo-nm);
        m = nm;
    }
    const float inv = 1.f / s;

    // ---- pass 2: probs + splits + chunked mean ----
    __nv_bfloat162* phv = (__nv_bfloat162*)(g_Ph + rbase);
    __nv_bfloat162* plv = (__nv_bfloat162*)(g_Pl + rbase);
    float4* pb4 = (float4*)pbuf[w];
    float4* mo4 = (float4*)(mean_out + (size_t)(b*2048 + q)*2048);

    for (int c = 0; c < 4; c++) {
        #pragma unroll
        for (int jj = 0; jj < 4; jj++) {
            int j = c*128 + jj*32 + l;
            float4 v = rowv[j], mk = mv[j], e;
            e.x = __expf(v.x+mk.x-m)*inv; e.y = __expf(v.y+mk.y-m)*inv;
            e.z = __expf(v.z+mk.z-m)*inv; e.w = __expf(v.w+mk.w-m)*inv;
            pb4[jj*32 + l] = e;
            __nv_bfloat16 h0=__float2bfloat16_rn(e.x), h1=__float2bfloat16_rn(e.y);
            __nv_bfloat16 h2=__float2bfloat16_rn(e.z), h3=__float2bfloat16_rn(e.w);
            phv[2*j]   = __nv_bfloat162(h0, h1);
            phv[2*j+1] = __nv_bfloat162(h2, h3);
            plv[2*j]   = __nv_bfloat162(__float2bfloat16_rn(e.x-__bfloat162float(h0)),
                                        __float2bfloat16_rn(e.y-__bfloat162float(h1)));
            plv[2*j+1] = __nv_bfloat162(__float2bfloat16_rn(e.z-__bfloat162float(h2)),
                                        __float2bfloat16_rn(e.w-__bfloat162float(h3)));
        }
        __syncthreads();
        if (t < 128) {
            float4 sm4 = {0.f,0.f,0.f,0.f};
            #pragma unroll
            for (int h = 0; h < 8; h++) {
                float4 p = ((float4*)pbuf[h])[t];
                sm4.x += p.x; sm4.y += p.y; sm4.z += p.z; sm4.w += p.w;
            }
            sm4.x *= 0.125f; sm4.y *= 0.125f; sm4.z *= 0.125f; sm4.w *= 0.125f;
            mo4[c*128 + t] = sm4;
        }
        __syncthreads();
    }
}

// ---------------- HMMA PV: ctx = (Ph+Pl) @ (Vth+Vtl)^T ----------------
#define PV_PAD  72
#define PV_PT   (128 * PV_PAD)
#define PV_VT   (64 * PV_PAD)
#define PV_SMEM ((2*PV_PT + 2*PV_VT) * 2)
__global__ __launch_bounds__(256)
void pv_mma()
{
    extern __shared__ __nv_bfloat16 smp[];
    __nv_bfloat16* PhT = smp;
    __nv_bfloat16* PlT = smp + PV_PT;
    __nv_bfloat16* VhT = smp + 2*PV_PT;
    __nv_bfloat16* VlT = VhT + PV_VT;

    const int t = threadIdx.x, lane = t & 31, wid = t >> 5;
    const int bh = blockIdx.z, b = bh >> 3, h = bh & 7;
    const int m0 = blockIdx.x * 128;

    const uint4* PhG = (const uint4*)(g_Ph  + ((size_t)bh*2048 + m0)*2048);
    const uint4* PlG = (const uint4*)(g_Pl  + ((size_t)bh*2048 + m0)*2048);
    const uint4* VhG = (const uint4*)(g_Vth + (size_t)bh*64*2048);
    const uint4* VlG = (const uint4*)(g_Vtl + (size_t)bh*64*2048);

    const int wm = (wid & 3) * 32, wn = (wid >> 2) * 32;
    const int arw = lane & 15, acg = (lane >> 4) * 8;
    const int brw = ((lane >> 4) << 3) + (lane & 7), bcg = ((lane >> 3) & 1) * 8;
    const uint32_t smb = smem_u32(smp);

    float acc[2][4][4];
    #pragma unroll
    for (int i=0;i<2;i++) for (int j=0;j<4;j++) for (int k=0;k<4;k++) acc[i][j][k]=0.f;

    const int pr = t >> 3, pc = t & 7;

    uint4 rp[4], rl[4], rvh[2], rvl[2];
    #pragma unroll
    for (int it = 0; it < 4; it++) {
        int r = pr + it*32;
        rp[it] = PhG[(size_t)r*256 + pc];
        rl[it] = PlG[(size_t)r*256 + pc];
    }
    #pragma unroll
    for (int it = 0; it < 2; it++) {
        int idx = t + it*256, r = idx >> 3, cc = idx & 7;
        rvh[it] = VhG[(size_t)r*256 + cc];
        rvl[it] = VlG[(size_t)r*256 + cc];
    }

    for (int c = 0; c < 32; c++) {
        #pragma unroll
        for (int it = 0; it < 4; it++) {
            int r = pr + it*32;
            ((uint4*)PhT)[r*9 + pc] = rp[it];
            ((uint4*)PlT)[r*9 + pc] = rl[it];
        }
        #pragma unroll
        for (int it = 0; it < 2; it++) {
            int idx = t + it*256, r = idx >> 3, cc = idx & 7;
            ((uint4*)VhT)[r*9 + cc] = rvh[it];
            ((uint4*)VlT)[r*9 + cc] = rvl[it];
        }
        __syncthreads();

        if (c < 31) {
            const int kq = (c+1) * 8;
            #pragma unroll
            for (int it = 0; it < 4; it++) {
                int r = pr + it*32;
                rp[it] = PhG[(size_t)r*256 + kq + pc];
                rl[it] = PlG[(size_t)r*256 + kq + pc];
            }
            #pragma unroll
            for (int it = 0; it < 2; it++) {
                int idx = t + it*256, r = idx >> 3, cc = idx & 7;
                rvh[it] = VhG[(size_t)r*256 + kq + cc];
                rvl[it] = VlG[(size_t)r*256 + kq + cc];
            }
        }

        const uint32_t PT2[2] = { smb,               smb + PV_PT*2 };
        const uint32_t VT2[2] = { smb + 2*PV_PT*2,   smb + 2*PV_PT*2 + PV_VT*2 };
        const int tp[3] = {0, 0, 1};
        const int tv[3] = {0, 1, 0};
        #pragma unroll
        for (int p = 0; p < 3; p++) {
            const uint32_t PT = PT2[tp[p]], VT = VT2[tv[p]];
            #pragma unroll
            for (int ks = 0; ks < 4; ks++) {
                uint32_t a[2][4], bfr[4][2];
                #pragma unroll
                for (int mi = 0; mi < 2; mi++) {
                    uint32_t addr = PT + ((wm + mi*16 + arw)*PV_PAD + ks*16 + acg)*2;
                    LDSM_X4(a[mi][0], a[mi][1], a[mi][2], a[mi][3], addr);
                }
                #pragma unroll
                for (int ng = 0; ng < 2; ng++) {
                    uint32_t addr = VT + ((wn + ng*16 + brw)*PV_PAD + ks*16 + bcg)*2;
                    uint32_t b0,b1,b2,b3;
                    LDSM_X4(b0, b1, b2, b3, addr);
                    bfr[ng*2][0]=b0; bfr[ng*2][1]=b1; bfr[ng*2+1][0]=b2; bfr[ng*2+1][1]=b3;
                }
                #pragma unroll
                for (int mi = 0; mi < 2; mi++)
                    #pragma unroll
                    for (int ni = 0; ni < 4; ni++)
                        MMA16816(acc[mi][ni], a[mi], bfr[ni]);
            }
        }
        __syncthreads();
    }

    float* dst = g_ctx + ((size_t)(b*2048 + m0))*512 + h*64;
    #pragma unroll
    for (int mi = 0; mi < 2; mi++) {
        #pragma unroll
        for (int ni = 0; ni < 4; ni++) {
            int row = wm + mi*16 + (lane >> 2);
            int col = wn + ni*8 + (lane & 3)*2;
            float2 v0 = { acc[mi][ni][0], acc[mi][ni][1] };
            float2 v1 = { acc[mi][ni][2], acc[mi][ni][3] };
            *(float2*)&dst[(size_t)row*512 + col]     = v0;
            *(float2*)&dst[(size_t)(row+8)*512 + col] = v1;
        }
    }
}

// ---------------- launch ----------------
extern "C" void kernel_launch(void* const* d_in, const int* in_sizes, int n_in,
                              void* d_out, int out_size)
{
    const float* Zq   = (const float*)d_in[0];
    const float* Zkv  = (const float*)d_in[1];
    const float* mask = (const float*)d_in[2];
    const float* Wqkv = (const float*)d_in[3];
    const float* Wout = (const float*)d_in[4];
    float* out   = (float*)d_out;
    float* meanp = out + (size_t)B_ * S_ * D_;

    float* Cp;
    cudaGetSymbolAddress((void**)&Cp, g_ctx);

    cudaFuncSetAttribute(scores_mma, cudaFuncAttributeMaxDynamicSharedMemorySize, SC_SMEM);
    cudaFuncSetAttribute(pv_mma,     cudaFuncAttributeMaxDynamicSharedMemorySize, PV_SMEM);

    const int M = B_ * S_;   // 8192

    // Q projection -> 3-way bf16 splits
    gemm_nn<1><<<dim3(4, M/128), 256>>>(Zq, Wqkv, nullptr, M, 512, 512, 3*D_, 0);

    // K|V projection -> K 3-way splits, V transposed 2-way splits
    gemm_nn<2><<<dim3(8, M/128), 256>>>(Zkv, Wqkv + D_, nullptr, M, 512, 512, 3*D_, 0);

    // scores via HMMA (6-term bf16 split ~= fp32)
    scores_mma<<<dim3(16, 16, 32), 256, SC_SMEM>>>();

    // two-pass softmax + mean + P bf16 split
    softmax_mean_k<<<dim3(S_, B_), 256>>>(mask, meanp);

    // ctx = P @ V via HMMA (3-term bf16 split)
    pv_mma<<<dim3(16, 1, 32), 256, PV_SMEM>>>();

    // out = ctx @ Wout (fp32)
    gemm_nn<0><<<dim3(4, M/128), 256>>>(Cp, Wout, out, M, 512, 512, 512, 512);
}

// round 13
// speedup vs baseline: 4.6052x; 1.0113x over previous
#include <cuda_runtime.h>
#include <cuda_bf16.h>
#include <cstdint>

#define B_   4
#define S_   2048
#define D_   512
#define H_   8
#define DK_  64
#define SCALE_ 0.125f

#define NQK ((size_t)B_*H_*S_*DK_)
#define NSS ((size_t)B_*H_*S_*S_)

// ---------------- scratch ----------------
__device__ __nv_bfloat16 g_Qh[NQK], g_Qm[NQK], g_Ql[NQK];
__device__ __nv_bfloat16 g_Kh[NQK], g_Km[NQK], g_Kl[NQK];
__device__ __nv_bfloat16 g_Vth[NQK], g_Vtl[NQK];      // transposed [bh][dk][s]
__device__ float         g_S[NSS];                     // masked, scaled scores
__device__ float         g_ctx[(size_t)B_*S_*D_];
__device__ float2        g_cstat[32][16][2048];        // [bh][kchunk][row]: (max, sumexp)
__device__ float2        g_stat[32][2048];             // [bh][row]: (max, 1/sum)

// ---------------- helpers ----------------
__device__ __forceinline__ uint32_t smem_u32(const void* p){
    uint32_t a; asm("{ .reg .u64 t; cvta.to.shared.u64 t,%1; cvt.u32.u64 %0,t; }":"=r"(a):"l"(p)); return a;
}
#define LDSM_X4(r0,r1,r2,r3,addr) \
    asm volatile("ldmatrix.sync.aligned.m8n8.x4.shared.b16 {%0,%1,%2,%3},[%4];" \
        :"=r"(r0),"=r"(r1),"=r"(r2),"=r"(r3):"r"(addr))
#define MMA16816(d,a,b) \
    asm volatile("mma.sync.aligned.m16n8k16.row.col.f32.bf16.bf16.f32 " \
        "{%0,%1,%2,%3},{%4,%5,%6,%7},{%8,%9},{%0,%1,%2,%3};" \
        : "+f"((d)[0]),"+f"((d)[1]),"+f"((d)[2]),"+f"((d)[3]) \
        : "r"((a)[0]),"r"((a)[1]),"r"((a)[2]),"r"((a)[3]),"r"((b)[0]),"r"((b)[1]))

__device__ __forceinline__ void split3(float v, __nv_bfloat16& h, __nv_bfloat16& m, __nv_bfloat16& l){
    h = __float2bfloat16_rn(v); float r  = v - __bfloat162float(h);
    m = __float2bfloat16_rn(r); float r2 = r - __bfloat162float(m);
    l = __float2bfloat16_rn(r2);
}

// ---------------- fp32 pipelined GEMM (NN) ----------------
// MODE 0: plain store. MODE 1: Q proj -> 3-way bf16 splits (packed stores).
// MODE 2: KV proj -> K 3-way splits (n0<512), V transposed 2-way splits (n0>=512).
template<int MODE>
__global__ __launch_bounds__(256)
void gemm_nn(const float* __restrict__ A, const float* __restrict__ Bw,
             float* __restrict__ C, int M, int K, int lda, int ldb, int ldc)
{
    __shared__ float As[16][132];
    __shared__ float Bs[16][128];
    const int t  = threadIdx.x;
    const int m0 = blockIdx.y * 128;
    const int n0 = blockIdx.x * 128;
    const int tm = t >> 4, tn = t & 15;
    const int ar = t >> 2, ac = (t & 3) << 2;
    const int br = t >> 5, bc = (t & 31) << 2;

    float4 pa[2], pb[2];
    #pragma unroll
    for (int i = 0; i < 2; i++)
        pa[i] = *(const float4*)&A[(size_t)(m0 + ar + i*64) * lda + ac];
    #pragma unroll
    for (int i = 0; i < 2; i++)
        pb[i] = *(const float4*)&Bw[(size_t)(br + i*8) * ldb + n0 + bc];

    float acc[8][8];
    #pragma unroll
    for (int i = 0; i < 8; i++)
        #pragma unroll
        for (int j = 0; j < 8; j++) acc[i][j] = 0.f;

    int k0 = 0;
    while (true) {
        #pragma unroll
        for (int i = 0; i < 2; i++) {
            As[ac+0][ar+i*64] = pa[i].x; As[ac+1][ar+i*64] = pa[i].y;
            As[ac+2][ar+i*64] = pa[i].z; As[ac+3][ar+i*64] = pa[i].w;
        }
        #pragma unroll
        for (int i = 0; i < 2; i++)
            *(float4*)&Bs[br + i*8][bc] = pb[i];
        __syncthreads();

        int kn = k0 + 16;
        bool more = (kn < K);
        if (more) {
            #pragma unroll
            for (int i = 0; i < 2; i++)
                pa[i] = *(const float4*)&A[(size_t)(m0 + ar + i*64) * lda + kn + ac];
            #pragma unroll
            for (int i = 0; i < 2; i++)
                pb[i] = *(const float4*)&Bw[(size_t)(kn + br + i*8) * ldb + n0 + bc];
        }
        #pragma unroll
        for (int k = 0; k < 16; k++) {
            float4 a0 = *(const float4*)&As[k][tm*8];
            float4 a1 = *(const float4*)&As[k][tm*8+4];
            float4 b0 = *(const float4*)&Bs[k][tn*8];
            float4 b1 = *(const float4*)&Bs[k][tn*8+4];
            float av[8] = {a0.x,a0.y,a0.z,a0.w,a1.x,a1.y,a1.z,a1.w};
            float bv[8] = {b0.x,b0.y,b0.z,b0.w,b1.x,b1.y,b1.z,b1.w};
            #pragma unroll
            for (int i = 0; i < 8; i++)
                #pragma unroll
                for (int j = 0; j < 8; j++)
                    acc[i][j] += av[i] * bv[j];
        }
        if (!more) break;
        __syncthreads();
        k0 = kn;
    }

    const int bb = m0 >> 11;
    const int s0 = (m0 & 2047) + tm*8;

    if (MODE == 0) {
        #pragma unroll
        for (int i = 0; i < 8; i++) {
            int gm = m0 + tm*8 + i;
            #pragma unroll
            for (int j = 0; j < 8; j++)
                C[(size_t)gm * ldc + n0 + tn*8 + j] = acc[i][j];
        }
    } else if (MODE == 1 || (MODE == 2 && n0 < 512)) {
        const int gn0 = n0 + tn*8;
        const int hh = gn0 >> 6, dk = gn0 & 63;
        __nv_bfloat16* d0 = (MODE == 1) ? g_Qh : g_Kh;
        __nv_bfloat16* d1 = (MODE == 1) ? g_Qm : g_Km;
        __nv_bfloat16* d2 = (MODE == 1) ? g_Ql : g_Kl;
        #pragma unroll
        for (int i = 0; i < 8; i++) {
            size_t qi = ((size_t)((bb<<3)+hh)*2048 + s0 + i)*64 + dk;
            __align__(16) __nv_bfloat16 xh[8], xm[8], xl[8];
            #pragma unroll
            for (int j = 0; j < 8; j++) split3(acc[i][j], xh[j], xm[j], xl[j]);
            *(uint4*)&d0[qi] = *(uint4*)xh;
            *(uint4*)&d1[qi] = *(uint4*)xm;
            *(uint4*)&d2[qi] = *(uint4*)xl;
        }
    } else {
        const int gn0 = n0 - 512 + tn*8;
        const int hh = gn0 >> 6, dk0 = gn0 & 63;
        #pragma unroll
        for (int j = 0; j < 8; j++) {
            __align__(16) __nv_bfloat16 vh[8], vl[8];
            #pragma unroll
            for (int i = 0; i < 8; i++) {
                float v = acc[i][j];
                vh[i] = __float2bfloat16_rn(v);
                vl[i] = __float2bfloat16_rn(v - __bfloat162float(vh[i]));
            }
            size_t vi = ((size_t)((bb<<3)+hh)*64 + dk0 + j)*2048 + s0;
            *(uint4*)&g_Vth[vi] = *(uint4*)vh;
            *(uint4*)&g_Vtl[vi] = *(uint4*)vl;
        }
    }
}

// ---------------- HMMA scores: S = QK^T*SCALE + mask, plus per-chunk row stats ----
#define SC_PAD   72
#define SC_TILE  (128 * SC_PAD)
#define SC_SMEM  (6 * SC_TILE * 2)
__global__ __launch_bounds__(256)
void scores_mma(const float* __restrict__ maskp)
{
    extern __shared__ __nv_bfloat16 smt[];
    const int t = threadIdx.x, lane = t & 31, wid = t >> 5;
    const int bh = blockIdx.z, m0 = blockIdx.y * 128, n0 = blockIdx.x * 128;

    {
        const size_t qoff = ((size_t)bh*2048 + m0)*64;
        const size_t koff = ((size_t)bh*2048 + n0)*64;
        const __nv_bfloat16* gsrc[6] = { g_Qh+qoff, g_Qm+qoff, g_Ql+qoff,
                                         g_Kh+koff, g_Km+koff, g_Kl+koff };
        #pragma unroll
        for (int tl = 0; tl < 6; tl++) {
            const uint4* src = (const uint4*)gsrc[tl];
            uint4* dst = (uint4*)(smt + tl*SC_TILE);
            #pragma unroll
            for (int it = 0; it < 4; it++) {
                int idx = t + it*256;
                int r = idx >> 3, cc = idx & 7;
                dst[r*9 + cc] = src[r*8 + cc];
            }
        }
    }
    __syncthreads();

    const int wm = (wid & 1) * 64, wn = (wid >> 1) * 32;
    const int arw = lane & 15, acg = (lane >> 4) * 8;
    const int brw = ((lane >> 4) << 3) + (lane & 7), bcg = ((lane >> 3) & 1) * 8;

    float acc[4][4][4];
    #pragma unroll
    for (int i=0;i<4;i++) for (int j=0;j<4;j++) for (int k=0;k<4;k++) acc[i][j][k]=0.f;

    const int pq[6] = {0,0,1,1,0,2};
    const int pk[6] = {0,1,0,1,2,0};
    const uint32_t smb = smem_u32(smt);

    for (int p = 0; p < 6; p++) {
        const uint32_t QT = smb + pq[p]*SC_TILE*2;
        const uint32_t KT = smb + (3+pk[p])*SC_TILE*2;
        #pragma unroll
        for (int ks = 0; ks < 4; ks++) {
            uint32_t a[4][4], bfr[4][2];
            #pragma unroll
            for (int mi = 0; mi < 4; mi++) {
                uint32_t addr = QT + ((wm + mi*16 + arw)*SC_PAD + ks*16 + acg)*2;
                LDSM_X4(a[mi][0], a[mi][1], a[mi][2], a[mi][3], addr);
            }
            #pragma unroll
            for (int ng = 0; ng < 2; ng++) {
                uint32_t addr = KT + ((wn + ng*16 + brw)*SC_PAD + ks*16 + bcg)*2;
                uint32_t b0,b1,b2,b3;
                LDSM_X4(b0, b1, b2, b3, addr);
                bfr[ng*2][0]=b0; bfr[ng*2][1]=b1; bfr[ng*2+1][0]=b2; bfr[ng*2+1][1]=b3;
            }
            #pragma unroll
            for (int mi = 0; mi < 4; mi++)
                #pragma unroll
                for (int ni = 0; ni < 4; ni++)
                    MMA16816(acc[mi][ni], a[mi], bfr[ni]);
        }
    }

    // ---- epilogue: scale + mask, per-row (max, sumexp) over this 128-col chunk ----
    __syncthreads();                      // smt reuse for warp stats
    float2* wstat = (float2*)smt;         // [128][4]

    float rm[8], rsum[8];
    #pragma unroll
    for (int mi = 0; mi < 4; mi++) {
        const int grow0 = m0 + wm + mi*16 + (lane>>2);
        #pragma unroll
        for (int ni = 0; ni < 4; ni++) {
            const int col = n0 + wn + ni*8 + (lane&3)*2;
            float2 mk0 = *(const float2*)&maskp[(size_t)grow0*2048 + col];
            float2 mk1 = *(const float2*)&maskp[(size_t)(grow0+8)*2048 + col];
            acc[mi][ni][0] = acc[mi][ni][0]*SCALE_ + mk0.x;
            acc[mi][ni][1] = acc[mi][ni][1]*SCALE_ + mk0.y;
            acc[mi][ni][2] = acc[mi][ni][2]*SCALE_ + mk1.x;
            acc[mi][ni][3] = acc[mi][ni][3]*SCALE_ + mk1.y;
        }
        float m0v = -1e30f, m1v = -1e30f;
        #pragma unroll
        for (int ni = 0; ni < 4; ni++) {
            m0v = fmaxf(m0v, fmaxf(acc[mi][ni][0], acc[mi][ni][1]));
            m1v = fmaxf(m1v, fmaxf(acc[mi][ni][2], acc[mi][ni][3]));
        }
        m0v = fmaxf(m0v, __shfl_xor_sync(0xffffffffu, m0v, 1));
        m0v = fmaxf(m0v, __shfl_xor_sync(0xffffffffu, m0v, 2));
        m1v = fmaxf(m1v, __shfl_xor_sync(0xffffffffu, m1v, 1));
        m1v = fmaxf(m1v, __shfl_xor_sync(0xffffffffu, m1v, 2));
        float s0 = 0.f, s1 = 0.f;
        #pragma unroll
        for (int ni = 0; ni < 4; ni++) {
            s0 += __expf(acc[mi][ni][0]-m0v) + __expf(acc[mi][ni][1]-m0v);
            s1 += __expf(acc[mi][ni][2]-m1v) + __expf(acc[mi][ni][3]-m1v);
        }
        s0 += __shfl_xor_sync(0xffffffffu, s0, 1);
        s0 += __shfl_xor_sync(0xffffffffu, s0, 2);
        s1 += __shfl_xor_sync(0xffffffffu, s1, 1);
        s1 += __shfl_xor_sync(0xffffffffu, s1, 2);
        rm[mi*2]=m0v; rsum[mi*2]=s0; rm[mi*2+1]=m1v; rsum[mi*2+1]=s1;
    }
    if ((lane & 3) == 0) {
        #pragma unroll
        for (int mi = 0; mi < 4; mi++) {
            int r = wm + mi*16 + (lane>>2);
            wstat[r*4 + (wid>>1)]     = make_float2(rm[mi*2],   rsum[mi*2]);
            wstat[(r+8)*4 + (wid>>1)] = make_float2(rm[mi*2+1], rsum[mi*2+1]);
        }
    }
    __syncthreads();
    if (t < 128) {
        float2 a = wstat[t*4+0], b2 = wstat[t*4+1], c2 = wstat[t*4+2], d2 = wstat[t*4+3];
        float m = fmaxf(fmaxf(a.x,b2.x), fmaxf(c2.x,d2.x));
        float s = a.y*__expf(a.x-m) + b2.y*__expf(b2.x-m)
                + c2.y*__expf(c2.x-m) + d2.y*__expf(d2.x-m);
        g_cstat[bh][n0>>7][m0+t] = make_float2(m, s);
    }

    // ---- store S (masked, scaled) ----
    float* Crow = g_S + (size_t)bh*2048*2048;
    #pragma unroll
    for (int mi = 0; mi < 4; mi++) {
        #pragma unroll
        for (int ni = 0; ni < 4; ni++) {
            int row = m0 + wm + mi*16 + (lane >> 2);
            int col = n0 + wn + ni*8 + (lane & 3)*2;
            float2 v0 = { acc[mi][ni][0], acc[mi][ni][1] };
            float2 v1 = { acc[mi][ni][2], acc[mi][ni][3] };
            *(float2*)&Crow[(size_t)row*2048 + col]     = v0;
            *(float2*)&Crow[(size_t)(row+8)*2048 + col] = v1;
        }
    }
}

// ---------------- combine chunk stats -> (max, 1/sum) per row ----------------
__global__ __launch_bounds__(256)
void combine_stats()
{
    const int bh = blockIdx.y;
    const int r  = blockIdx.x * 256 + threadIdx.x;
    float2 v[16];
    float m = -1e30f;
    #pragma unroll
    for (int c = 0; c < 16; c++) { v[c] = g_cstat[bh][c][r]; m = fmaxf(m, v[c].x); }
    float s = 0.f;
    #pragma unroll
    for (int c = 0; c < 16; c++) s += v[c].y * __expf(v[c].x - m);
    g_stat[bh][r] = make_float2(m, 1.f / s);
}

// ---------------- single-pass mean over heads ----------------
// Block = (q, b), 256 threads, warp w = head w. S already masked; stats known.
__global__ __launch_bounds__(256)
void softmax_mean_k(float* __restrict__ mean_out)
{
    __shared__ __align__(16) float pbuf[8][512];

    const int t = threadIdx.x, w = t >> 5, l = t & 31;
    const int q = blockIdx.x, b = blockIdx.y;

    const float2 st = g_stat[b*8 + w][q];
    const float m = st.x, inv = st.y;

    const size_t rbase = ((size_t)(b*8 + w)*2048 + q)*2048;
    const float4* rowv = (const float4*)(g_S + rbase);
    float4* pb4 = (float4*)pbuf[w];
    float4* mo4 = (float4*)(mean_out + (size_t)(b*2048 + q)*2048);

    for (int c = 0; c < 4; c++) {
        #pragma unroll
        for (int jj = 0; jj < 4; jj++) {
            int j = c*128 + jj*32 + l;
            float4 v = rowv[j], e;
            e.x = __expf(v.x-m)*inv; e.y = __expf(v.y-m)*inv;
            e.z = __expf(v.z-m)*inv; e.w = __expf(v.w-m)*inv;
            pb4[jj*32 + l] = e;
        }
        __syncthreads();
        if (t < 128) {
            float4 sm4 = {0.f,0.f,0.f,0.f};
            #pragma unroll
            for (int h = 0; h < 8; h++) {
                float4 p = ((float4*)pbuf[h])[t];
                sm4.x += p.x; sm4.y += p.y; sm4.z += p.z; sm4.w += p.w;
            }
            sm4.x *= 0.125f; sm4.y *= 0.125f; sm4.z *= 0.125f; sm4.w *= 0.125f;
            mo4[c*128 + t] = sm4;
        }
        __syncthreads();
    }
}

// ---------------- HMMA PV: ctx = P @ V^T, P generated inline from S ----------------
#define PV_PAD  72
#define PV_PT   (128 * PV_PAD)
#define PV_VT   (64 * PV_PAD)
#define PV_SMEM (((2*PV_PT + 2*PV_VT) * 2) + 1024)
__global__ __launch_bounds__(256)
void pv_mma()
{
    extern __shared__ __nv_bfloat16 smp[];
    __nv_bfloat16* PhT = smp;
    __nv_bfloat16* PlT = smp + PV_PT;
    __nv_bfloat16* VhT = smp + 2*PV_PT;
    __nv_bfloat16* VlT = VhT + PV_VT;
    float2* rstat = (float2*)(smp + 2*PV_PT + 2*PV_VT);   // [128]

    const int t = threadIdx.x, lane = t & 31, wid = t >> 5;
    const int bh = blockIdx.z, b = bh >> 3, h = bh & 7;
    const int m0 = blockIdx.x * 128;

    const float4* SG  = (const float4*)(g_S   + ((size_t)bh*2048 + m0)*2048);
    const uint4*  VhG = (const uint4*)(g_Vth + (size_t)bh*64*2048);
    const uint4*  VlG = (const uint4*)(g_Vtl + (size_t)bh*64*2048);

    if (t < 128) rstat[t] = g_stat[bh][m0 + t];

    const int wm = (wid & 3) * 32, wn = (wid >> 2) * 32;
    const int arw = lane & 15, acg = (lane >> 4) * 8;
    const int brw = ((lane >> 4) << 3) + (lane & 7), bcg = ((lane >> 3) & 1) * 8;
    const uint32_t smb = smem_u32(smp);

    float acc[2][4][4];
    #pragma unroll
    for (int i=0;i<2;i++) for (int j=0;j<4;j++) for (int k=0;k<4;k++) acc[i][j][k]=0.f;

    float4 rs[8];
    uint4 rvh[2], rvl[2];
    #pragma unroll
    for (int it = 0; it < 8; it++) {
        int idx = t + it*256, r = idx >> 4, c4 = idx & 15;
        rs[it] = SG[(size_t)r*512 + c4];
    }
    #pragma unroll
    for (int it = 0; it < 2; it++) {
        int idx = t + it*256, r = idx >> 3, cc = idx & 7;
        rvh[it] = VhG[(size_t)r*256 + cc];
        rvl[it] = VlG[(size_t)r*256 + cc];
    }
    __syncthreads();   // rstat ready

    for (int c = 0; c < 32; c++) {
        // convert prefetched S chunk -> P splits in smem
        #pragma unroll
        for (int it = 0; it < 8; it++) {
            int idx = t + it*256, r = idx >> 4, c4 = idx & 15;
            float2 st = rstat[r];
            float4 s4 = rs[it];
            float e0 = __expf(s4.x - st.x)*st.y;
            float e1 = __expf(s4.y - st.x)*st.y;
            float e2 = __expf(s4.z - st.x)*st.y;
            float e3 = __expf(s4.w - st.x)*st.y;
            __nv_bfloat16 h0=__float2bfloat16_rn(e0), h1=__float2bfloat16_rn(e1);
            __nv_bfloat16 h2=__float2bfloat16_rn(e2), h3=__float2bfloat16_rn(e3);
            __nv_bfloat162 ph01(h0,h1), ph23(h2,h3);
            __nv_bfloat162 pl01(__float2bfloat16_rn(e0-__bfloat162float(h0)),
                                __float2bfloat16_rn(e1-__bfloat162float(h1)));
            __nv_bfloat162 pl23(__float2bfloat16_rn(e2-__bfloat162float(h2)),
                                __float2bfloat16_rn(e3-__bfloat162float(h3)));
            __nv_bfloat162* dph = (__nv_bfloat162*)&PhT[r*PV_PAD + c4*4];
            __nv_bfloat162* dpl = (__nv_bfloat162*)&PlT[r*PV_PAD + c4*4];
            dph[0] = ph01; dph[1] = ph23;
            dpl[0] = pl01; dpl[1] = pl23;
        }
        #pragma unroll
        for (int it = 0; it < 2; it++) {
            int idx = t + it*256, r = idx >> 3, cc = idx & 7;
            ((uint4*)VhT)[r*9 + cc] = rvh[it];
            ((uint4*)VlT)[r*9 + cc] = rvl[it];
        }
        __syncthreads();

        if (c < 31) {
            const int kq4 = (c+1) * 16;
            const int kq  = (c+1) * 8;
            #pragma unroll
            for (int it = 0; it < 8; it++) {
                int idx = t + it*256, r = idx >> 4, c4 = idx & 15;
                rs[it] = SG[(size_t)r*512 + kq4 + c4];
            }
            #pragma unroll
            for (int it = 0; it < 2; it++) {
                int idx = t + it*256, r = idx >> 3, cc = idx & 7;
                rvh[it] = VhG[(size_t)r*256 + kq + cc];
                rvl[it] = VlG[(size_t)r*256 + kq + cc];
            }
        }

        const uint32_t PT2[2] = { smb,               smb + PV_PT*2 };
        const uint32_t VT2[2] = { smb + 2*PV_PT*2,   smb + 2*PV_PT*2 + PV_VT*2 };
        const int tp[3] = {0, 0, 1};
        const int tv[3] = {0, 1, 0};
        #pragma unroll
        for (int p = 0; p < 3; p++) {
            const uint32_t PT = PT2[tp[p]], VT = VT2[tv[p]];
            #pragma unroll
            for (int ks = 0; ks < 4; ks++) {
                uint32_t a[2][4], bfr[4][2];
                #pragma unroll
                for (int mi = 0; mi < 2; mi++) {
                    uint32_t addr = PT + ((wm + mi*16 + arw)*PV_PAD + ks*16 + acg)*2;
                    LDSM_X4(a[mi][0], a[mi][1], a[mi][2], a[mi][3], addr);
                }
                #pragma unroll
                for (int ng = 0; ng < 2; ng++) {
                    uint32_t addr = VT + ((wn + ng*16 + brw)*PV_PAD + ks*16 + bcg)*2;
                    uint32_t b0,b1,b2,b3;
                    LDSM_X4(b0, b1, b2, b3, addr);
                    bfr[ng*2][0]=b0; bfr[ng*2][1]=b1; bfr[ng*2+1][0]=b2; bfr[ng*2+1][1]=b3;
                }
                #pragma unroll
                for (int mi = 0; mi < 2; mi++)
                    #pragma unroll
                    for (int ni = 0; ni < 4; ni++)
                        MMA16816(acc[mi][ni], a[mi], bfr[ni]);
            }
        }
        __syncthreads();
    }

    float* dst = g_ctx + ((size_t)(b*2048 + m0))*512 + h*64;
    #pragma unroll
    for (int mi = 0; mi < 2; mi++) {
        #pragma unroll
        for (int ni = 0; ni < 4; ni++) {
            int row = wm + mi*16 + (lane >> 2);
            int col = wn + ni*8 + (lane & 3)*2;
            float2 v0 = { acc[mi][ni][0], acc[mi][ni][1] };
            float2 v1 = { acc[mi][ni][2], acc[mi][ni][3] };
            *(float2*)&dst[(size_t)row*512 + col]     = v0;
            *(float2*)&dst[(size_t)(row+8)*512 + col] = v1;
        }
    }
}

// ---------------- launch ----------------
extern "C" void kernel_launch(void* const* d_in, const int* in_sizes, int n_in,
                              void* d_out, int out_size)
{
    const float* Zq   = (const float*)d_in[0];
    const float* Zkv  = (const float*)d_in[1];
    const float* mask = (const float*)d_in[2];
    const float* Wqkv = (const float*)d_in[3];
    const float* Wout = (const float*)d_in[4];
    float* out   = (float*)d_out;
    float* meanp = out + (size_t)B_ * S_ * D_;

    float* Cp;
    cudaGetSymbolAddress((void**)&Cp, g_ctx);

    cudaFuncSetAttribute(scores_mma, cudaFuncAttributeMaxDynamicSharedMemorySize, SC_SMEM);
    cudaFuncSetAttribute(pv_mma,     cudaFuncAttributeMaxDynamicSharedMemorySize, PV_SMEM);

    const int M = B_ * S_;   // 8192

    // Q projection -> 3-way bf16 splits
    gemm_nn<1><<<dim3(4, M/128), 256>>>(Zq, Wqkv, nullptr, M, 512, 512, 3*D_, 0);

    // K|V projection -> K 3-way splits, V transposed 2-way splits
    gemm_nn<2><<<dim3(8, M/128), 256>>>(Zkv, Wqkv + D_, nullptr, M, 512, 512, 3*D_, 0);

    // scores via HMMA (6-term bf16 split), fused mask + chunk softmax stats
    scores_mma<<<dim3(16, 16, 32), 256, SC_SMEM>>>(mask);

    // fold chunk stats into per-row (max, 1/sum)
    combine_stats<<<dim3(8, 32), 256>>>();

    // single-pass mean over heads
    softmax_mean_k<<<dim3(S_, B_), 256>>>(meanp);

    // ctx = P @ V via HMMA (3-term bf16 split), P generated inline from S
    pv_mma<<<dim3(16, 1, 32), 256, PV_SMEM>>>();

    // out = ctx @ Wout (fp32)
    gemm_nn<0><<<dim3(4, M/128), 256>>>(Cp, Wout, out, M, 512, 512, 512, 512);
}

// round 14
// speedup vs baseline: 5.8589x; 1.2722x over previous
#include <cuda_runtime.h>
#include <cuda_bf16.h>
#include <cstdint>

#define B_   4
#define S_   2048
#define D_   512
#define H_   8
#define DK_  64
#define SCALE_ 0.125f

#define NQK ((size_t)B_*H_*S_*DK_)
#define NSS ((size_t)B_*H_*S_*S_)
#define NMD ((size_t)B_*S_*D_)

// ---------------- scratch ----------------
// 2-way input splits (pre-projection)
__device__ __nv_bfloat16 g_Xqh[NMD], g_Xql[NMD];       // Zq  [m][512]
__device__ __nv_bfloat16 g_Xkh[NMD], g_Xkl[NMD];       // Zkv [m][512]
__device__ __nv_bfloat16 g_Wh[512*1536], g_Wl[512*1536];   // Wqkv [k][n]
__device__ __nv_bfloat16 g_Woh[512*512], g_Wol[512*512];   // Wout [k][n]
// post-projection operand splits
__device__ __nv_bfloat16 g_Qh[NQK], g_Qm[NQK], g_Ql[NQK]; // [bh][s][64]
__device__ __nv_bfloat16 g_Kh[NQK], g_Km[NQK], g_Kl[NQK];
__device__ __nv_bfloat16 g_Vh[NQK], g_Vl[NQK];            // natural [bh][s][64]
__device__ __nv_bfloat16 g_Ch[NMD], g_Cl[NMD];            // ctx splits [m][512]
__device__ float         g_S[NSS];                         // masked, scaled scores
__device__ float2        g_cstat[32][16][2048];
__device__ float2        g_stat[32][2048];

// ---------------- helpers ----------------
__device__ __forceinline__ uint32_t smem_u32(const void* p){
    uint32_t a; asm("{ .reg .u64 t; cvta.to.shared.u64 t,%1; cvt.u32.u64 %0,t; }":"=r"(a):"l"(p)); return a;
}
#define LDSM_X4(r0,r1,r2,r3,addr) \
    asm volatile("ldmatrix.sync.aligned.m8n8.x4.shared.b16 {%0,%1,%2,%3},[%4];" \
        :"=r"(r0),"=r"(r1),"=r"(r2),"=r"(r3):"r"(addr))
#define LDSM_X4_T(r0,r1,r2,r3,addr) \
    asm volatile("ldmatrix.sync.aligned.m8n8.x4.trans.shared.b16 {%0,%1,%2,%3},[%4];" \
        :"=r"(r0),"=r"(r1),"=r"(r2),"=r"(r3):"r"(addr))
#define MMA16816(d,a,b) \
    asm volatile("mma.sync.aligned.m16n8k16.row.col.f32.bf16.bf16.f32 " \
        "{%0,%1,%2,%3},{%4,%5,%6,%7},{%8,%9},{%0,%1,%2,%3};" \
        : "+f"((d)[0]),"+f"((d)[1]),"+f"((d)[2]),"+f"((d)[3]) \
        : "r"((a)[0]),"r"((a)[1]),"r"((a)[2]),"r"((a)[3]),"r"((b)[0]),"r"((b)[1]))

__device__ __forceinline__ void split3(float v, __nv_bfloat16& h, __nv_bfloat16& m, __nv_bfloat16& l){
    h = __float2bfloat16_rn(v); float r  = v - __bfloat162float(h);
    m = __float2bfloat16_rn(r); float r2 = r - __bfloat162float(m);
    l = __float2bfloat16_rn(r2);
}

// ---------------- elementwise 2-way split ----------------
__global__ __launch_bounds__(256)
void split2(const float4* __restrict__ src, __nv_bfloat162* __restrict__ h2,
            __nv_bfloat162* __restrict__ l2)
{
    size_t i = (size_t)blockIdx.x * 256 + threadIdx.x;
    float4 v = src[i];
    __nv_bfloat16 h0=__float2bfloat16_rn(v.x), h1=__float2bfloat16_rn(v.y);
    __nv_bfloat16 h2v=__float2bfloat16_rn(v.z), h3=__float2bfloat16_rn(v.w);
    h2[2*i]   = __nv_bfloat162(h0,h1);
    h2[2*i+1] = __nv_bfloat162(h2v,h3);
    l2[2*i]   = __nv_bfloat162(__float2bfloat16_rn(v.x-__bfloat162float(h0)),
                               __float2bfloat16_rn(v.y-__bfloat162float(h1)));
    l2[2*i+1] = __nv_bfloat162(__float2bfloat16_rn(v.z-__bfloat162float(h2v)),
                               __float2bfloat16_rn(v.w-__bfloat162float(h3)));
}

// ---------------- HMMA projection GEMM: C = (Ah+Al) @ (Bh+Bl), K=512 ----------------
// 3-term: AhBh + AhBl + AlBh. A [m][512] splits, B [k][n] row-major splits (trans ldsm).
// CTA 128x128, 8 warps (2m x 4n). K chunks of 64.
// MODE 0: plain fp32 store to C (ldc=512). MODE 1: Q 3-way split. MODE 2: KV (K 3-way / V 2-way).
#define PR_A   (128*72)
#define PR_B   (64*136)
#define PR_SMEM ((2*PR_A + 2*PR_B)*2)
template<int MODE>
__global__ __launch_bounds__(256)
void hmma_proj(const __nv_bfloat16* __restrict__ Ah_, const __nv_bfloat16* __restrict__ Al_,
               const __nv_bfloat16* __restrict__ Bh_, const __nv_bfloat16* __restrict__ Bl_,
               float* __restrict__ C, int ldb)
{
    extern __shared__ __nv_bfloat16 smb[];
    __nv_bfloat16* AhT = smb;
    __nv_bfloat16* AlT = smb + PR_A;
    __nv_bfloat16* BhT = smb + 2*PR_A;
    __nv_bfloat16* BlT = BhT + PR_B;

    const int t = threadIdx.x, lane = t & 31, wid = t >> 5;
    const int m0 = blockIdx.y * 128, n0 = blockIdx.x * 128;
    const int ldb4 = ldb >> 3, n04 = n0 >> 3;

    const uint4* AhG = (const uint4*)Ah_;
    const uint4* AlG = (const uint4*)Al_;
    const uint4* BhG = (const uint4*)Bh_;
    const uint4* BlG = (const uint4*)Bl_;

    const int wm = (wid & 1) * 64, wn = (wid >> 1) * 32;
    const int arw = lane & 15, acg = (lane >> 4) * 8;
    const int tkr = ((lane >> 3) & 1) * 8 + (lane & 7);   // k-row within 16 (trans)
    const int tnc = (lane >> 4) * 8;                      // n-col 0/8 (trans)
    const uint32_t smba = smem_u32(smb);

    float acc[4][4][4];
    #pragma unroll
    for (int i=0;i<4;i++) for (int j=0;j<4;j++) for (int k=0;k<4;k++) acc[i][j][k]=0.f;

    for (int c = 0; c < 8; c++) {
        if (c) __syncthreads();
        // A tiles: 128 rows x 8 uint4
        #pragma unroll
        for (int it = 0; it < 4; it++) {
            int idx = t + it*256, r = idx >> 3, cc = idx & 7;
            size_t si = (size_t)(m0 + r)*64 + c*8 + cc;
            ((uint4*)AhT)[r*9 + cc] = AhG[si];
            ((uint4*)AlT)[r*9 + cc] = AlG[si];
        }
        // B tiles: 64 k-rows x 16 uint4
        #pragma unroll
        for (int it = 0; it < 4; it++) {
            int idx = t + it*256, r = idx >> 4, cc = idx & 15;
            size_t si = (size_t)(c*64 + r)*ldb4 + n04 + cc;
            ((uint4*)BhT)[r*17 + cc] = BhG[si];
            ((uint4*)BlT)[r*17 + cc] = BlG[si];
        }
        __syncthreads();

        const uint32_t AT2[2] = { smba, smba + PR_A*2 };
        const uint32_t BT2[2] = { smba + 2*PR_A*2, smba + 2*PR_A*2 + PR_B*2 };
        const int ta[3] = {0,0,1};
        const int tb[3] = {0,1,0};
        #pragma unroll
        for (int p = 0; p < 3; p++) {
            const uint32_t AT = AT2[ta[p]], BT = BT2[tb[p]];
            #pragma unroll
            for (int ks = 0; ks < 4; ks++) {
                uint32_t a[4][4], bfr[4][2];
                #pragma unroll
                for (int mi = 0; mi < 4; mi++) {
                    uint32_t addr = AT + ((wm + mi*16 + arw)*72 + ks*16 + acg)*2;
                    LDSM_X4(a[mi][0], a[mi][1], a[mi][2], a[mi][3], addr);
                }
                #pragma unroll
                for (int ng = 0; ng < 2; ng++) {
                    uint32_t addr = BT + ((ks*16 + tkr)*136 + wn + ng*16 + tnc)*2;
                    uint32_t b0,b1,b2,b3;
                    LDSM_X4_T(b0, b1, b2, b3, addr);
                    bfr[ng*2][0]=b0; bfr[ng*2][1]=b1; bfr[ng*2+1][0]=b2; bfr[ng*2+1][1]=b3;
                }
                #pragma unroll
                for (int mi = 0; mi < 4; mi++)
                    #pragma unroll
                    for (int ni = 0; ni < 4; ni++)
                        MMA16816(acc[mi][ni], a[mi], bfr[ni]);
            }
        }
    }

    // ---- epilogue ----
    #pragma unroll
    for (int mi = 0; mi < 4; mi++) {
        #pragma unroll
        for (int ni = 0; ni < 4; ni++) {
            const int row = m0 + wm + mi*16 + (lane >> 2);
            const int col = wn + ni*8 + (lane & 3)*2;
            float d0 = acc[mi][ni][0], d1 = acc[mi][ni][1];
            float d2 = acc[mi][ni][2], d3 = acc[mi][ni][3];
            if (MODE == 0) {
                *(float2*)&C[(size_t)row*512 + n0 + col]     = make_float2(d0, d1);
                *(float2*)&C[(size_t)(row+8)*512 + n0 + col] = make_float2(d2, d3);
            } else {
                const int gn = n0 + col;
                const int b = row >> 11, s = row & 2047;
                if (MODE == 1 || gn < 512) {
                    const int hh = (gn & 511) >> 6, dk = gn & 63;
                    size_t base = ((size_t)((b<<3)+hh)*2048 + s)*64 + dk;
                    __nv_bfloat16 xh0,xm0,xl0, xh1,xm1,xl1;
                    split3(d0, xh0, xm0, xl0); split3(d1, xh1, xm1, xl1);
                    __nv_bfloat16* p0 = (MODE==1) ? g_Qh : g_Kh;
                    __nv_bfloat16* p1 = (MODE==1) ? g_Qm : g_Km;
                    __nv_bfloat16* p2 = (MODE==1) ? g_Ql : g_Kl;
                    *(__nv_bfloat162*)&p0[base] = __nv_bfloat162(xh0, xh1);
                    *(__nv_bfloat162*)&p1[base] = __nv_bfloat162(xm0, xm1);
                    *(__nv_bfloat162*)&p2[base] = __nv_bfloat162(xl0, xl1);
                    split3(d2, xh0, xm0, xl0); split3(d3, xh1, xm1, xl1);
                    *(__nv_bfloat162*)&p0[base+512] = __nv_bfloat162(xh0, xh1);
                    *(__nv_bfloat162*)&p1[base+512] = __nv_bfloat162(xm0, xm1);
                    *(__nv_bfloat162*)&p2[base+512] = __nv_bfloat162(xl0, xl1);
                } else {
                    const int gn2 = gn - 512;
                    const int hh = gn2 >> 6, dk = gn2 & 63;
                    size_t base = ((size_t)((b<<3)+hh)*2048 + s)*64 + dk;
                    __nv_bfloat16 h0=__float2bfloat16_rn(d0), h1=__float2bfloat16_rn(d1);
                    *(__nv_bfloat162*)&g_Vh[base] = __nv_bfloat162(h0, h1);
                    *(__nv_bfloat162*)&g_Vl[base] = __nv_bfloat162(
                        __float2bfloat16_rn(d0-__bfloat162float(h0)),
                        __float2bfloat16_rn(d1-__bfloat162float(h1)));
                    __nv_bfloat16 h2=__float2bfloat16_rn(d2), h3=__float2bfloat16_rn(d3);
                    *(__nv_bfloat162*)&g_Vh[base+512] = __nv_bfloat162(h2, h3);
                    *(__nv_bfloat162*)&g_Vl[base+512] = __nv_bfloat162(
                        __float2bfloat16_rn(d2-__bfloat162float(h2)),
                        __float2bfloat16_rn(d3-__bfloat162float(h3)));
                }
            }
        }
    }
}

// ---------------- HMMA scores: S = QK^T*SCALE + mask, plus per-chunk row stats ----
#define SC_PAD   72
#define SC_TILE  (128 * SC_PAD)
#define SC_SMEM  (6 * SC_TILE * 2)
__global__ __launch_bounds__(256)
void scores_mma(const float* __restrict__ maskp)
{
    extern __shared__ __nv_bfloat16 smt[];
    const int t = threadIdx.x, lane = t & 31, wid = t >> 5;
    const int bh = blockIdx.z, m0 = blockIdx.y * 128, n0 = blockIdx.x * 128;

    {
        const size_t qoff = ((size_t)bh*2048 + m0)*64;
        const size_t koff = ((size_t)bh*2048 + n0)*64;
        const __nv_bfloat16* gsrc[6] = { g_Qh+qoff, g_Qm+qoff, g_Ql+qoff,
                                         g_Kh+koff, g_Km+koff, g_Kl+koff };
        #pragma unroll
        for (int tl = 0; tl < 6; tl++) {
            const uint4* src = (const uint4*)gsrc[tl];
            uint4* dst = (uint4*)(smt + tl*SC_TILE);
            #pragma unroll
            for (int it = 0; it < 4; it++) {
                int idx = t + it*256;
                int r = idx >> 3, cc = idx & 7;
                dst[r*9 + cc] = src[r*8 + cc];
            }
        }
    }
    __syncthreads();

    const int wm = (wid & 1) * 64, wn = (wid >> 1) * 32;
    const int arw = lane & 15, acg = (lane >> 4) * 8;
    const int brw = ((lane >> 4) << 3) + (lane & 7), bcg = ((lane >> 3) & 1) * 8;

    float acc[4][4][4];
    #pragma unroll
    for (int i=0;i<4;i++) for (int j=0;j<4;j++) for (int k=0;k<4;k++) acc[i][j][k]=0.f;

    const int pq[6] = {0,0,1,1,0,2};
    const int pk[6] = {0,1,0,1,2,0};
    const uint32_t smb = smem_u32(smt);

    for (int p = 0; p < 6; p++) {
        const uint32_t QT = smb + pq[p]*SC_TILE*2;
        const uint32_t KT = smb + (3+pk[p])*SC_TILE*2;
        #pragma unroll
        for (int ks = 0; ks < 4; ks++) {
            uint32_t a[4][4], bfr[4][2];
            #pragma unroll
            for (int mi = 0; mi < 4; mi++) {
                uint32_t addr = QT + ((wm + mi*16 + arw)*SC_PAD + ks*16 + acg)*2;
                LDSM_X4(a[mi][0], a[mi][1], a[mi][2], a[mi][3], addr);
            }
            #pragma unroll
            for (int ng = 0; ng < 2; ng++) {
                uint32_t addr = KT + ((wn + ng*16 + brw)*SC_PAD + ks*16 + bcg)*2;
                uint32_t b0,b1,b2,b3;
                LDSM_X4(b0, b1, b2, b3, addr);
                bfr[ng*2][0]=b0; bfr[ng*2][1]=b1; bfr[ng*2+1][0]=b2; bfr[ng*2+1][1]=b3;
            }
            #pragma unroll
            for (int mi = 0; mi < 4; mi++)
                #pragma unroll
                for (int ni = 0; ni < 4; ni++)
                    MMA16816(acc[mi][ni], a[mi], bfr[ni]);
        }
    }

    __syncthreads();
    float2* wstat = (float2*)smt;

    float rm[8], rsum[8];
    #pragma unroll
    for (int mi = 0; mi < 4; mi++) {
        const int grow0 = m0 + wm + mi*16 + (lane>>2);
        #pragma unroll
        for (int ni = 0; ni < 4; ni++) {
            const int col = n0 + wn + ni*8 + (lane&3)*2;
            float2 mk0 = *(const float2*)&maskp[(size_t)grow0*2048 + col];
            float2 mk1 = *(const float2*)&maskp[(size_t)(grow0+8)*2048 + col];
            acc[mi][ni][0] = acc[mi][ni][0]*SCALE_ + mk0.x;
            acc[mi][ni][1] = acc[mi][ni][1]*SCALE_ + mk0.y;
            acc[mi][ni][2] = acc[mi][ni][2]*SCALE_ + mk1.x;
            acc[mi][ni][3] = acc[mi][ni][3]*SCALE_ + mk1.y;
        }
        float m0v = -1e30f, m1v = -1e30f;
        #pragma unroll
        for (int ni = 0; ni < 4; ni++) {
            m0v = fmaxf(m0v, fmaxf(acc[mi][ni][0], acc[mi][ni][1]));
            m1v = fmaxf(m1v, fmaxf(acc[mi][ni][2], acc[mi][ni][3]));
        }
        m0v = fmaxf(m0v, __shfl_xor_sync(0xffffffffu, m0v, 1));
        m0v = fmaxf(m0v, __shfl_xor_sync(0xffffffffu, m0v, 2));
        m1v = fmaxf(m1v, __shfl_xor_sync(0xffffffffu, m1v, 1));
        m1v = fmaxf(m1v, __shfl_xor_sync(0xffffffffu, m1v, 2));
        float s0 = 0.f, s1 = 0.f;
        #pragma unroll
        for (int ni = 0; ni < 4; ni++) {
            s0 += __expf(acc[mi][ni][0]-m0v) + __expf(acc[mi][ni][1]-m0v);
            s1 += __expf(acc[mi][ni][2]-m1v) + __expf(acc[mi][ni][3]-m1v);
        }
        s0 += __shfl_xor_sync(0xffffffffu, s0, 1);
        s0 += __shfl_xor_sync(0xffffffffu, s0, 2);
        s1 += __shfl_xor_sync(0xffffffffu, s1, 1);
        s1 += __shfl_xor_sync(0xffffffffu, s1, 2);
        rm[mi*2]=m0v; rsum[mi*2]=s0; rm[mi*2+1]=m1v; rsum[mi*2+1]=s1;
    }
    if ((lane & 3) == 0) {
        #pragma unroll
        for (int mi = 0; mi < 4; mi++) {
            int r = wm + mi*16 + (lane>>2);
            wstat[r*4 + (wid>>1)]     = make_float2(rm[mi*2],   rsum[mi*2]);
            wstat[(r+8)*4 + (wid>>1)] = make_float2(rm[mi*2+1], rsum[mi*2+1]);
        }
    }
    __syncthreads();
    if (t < 128) {
        float2 a = wstat[t*4+0], b2 = wstat[t*4+1], c2 = wstat[t*4+2], d2 = wstat[t*4+3];
        float m = fmaxf(fmaxf(a.x,b2.x), fmaxf(c2.x,d2.x));
        float s = a.y*__expf(a.x-m) + b2.y*__expf(b2.x-m)
                + c2.y*__expf(c2.x-m) + d2.y*__expf(d2.x-m);
        g_cstat[bh][n0>>7][m0+t] = make_float2(m, s);
    }

    float* Crow = g_S + (size_t)bh*2048*2048;
    #pragma unroll
    for (int mi = 0; mi < 4; mi++) {
        #pragma unroll
        for (int ni = 0; ni < 4; ni++) {
            int row = m0 + wm + mi*16 + (lane >> 2);
            int col = n0 + wn + ni*8 + (lane & 3)*2;
            float2 v0 = { acc[mi][ni][0], acc[mi][ni][1] };
            float2 v1 = { acc[mi][ni][2], acc[mi][ni][3] };
            *(float2*)&Crow[(size_t)row*2048 + col]     = v0;
            *(float2*)&Crow[(size_t)(row+8)*2048 + col] = v1;
        }
    }
}

// ---------------- combine chunk stats -> (max, 1/sum) per row ----------------
__global__ __launch_bounds__(256)
void combine_stats()
{
    const int bh = blockIdx.y;
    const int r  = blockIdx.x * 256 + threadIdx.x;
    float2 v[16];
    float m = -1e30f;
    #pragma unroll
    for (int c = 0; c < 16; c++) { v[c] = g_cstat[bh][c][r]; m = fmaxf(m, v[c].x); }
    float s = 0.f;
    #pragma unroll
    for (int c = 0; c < 16; c++) s += v[c].y * __expf(v[c].x - m);
    g_stat[bh][r] = make_float2(m, 1.f / s);
}

// ---------------- single-pass mean over heads ----------------
__global__ __launch_bounds__(256)
void softmax_mean_k(float* __restrict__ mean_out)
{
    __shared__ __align__(16) float pbuf[8][512];

    const int t = threadIdx.x, w = t >> 5, l = t & 31;
    const int q = blockIdx.x, b = blockIdx.y;

    const float2 st = g_stat[b*8 + w][q];
    const float m = st.x, inv = st.y;

    const size_t rbase = ((size_t)(b*8 + w)*2048 + q)*2048;
    const float4* rowv = (const float4*)(g_S + rbase);
    float4* pb4 = (float4*)pbuf[w];
    float4* mo4 = (float4*)(mean_out + (size_t)(b*2048 + q)*2048);

    for (int c = 0; c < 4; c++) {
        #pragma unroll
        for (int jj = 0; jj < 4; jj++) {
            int j = c*128 + jj*32 + l;
            float4 v = rowv[j], e;
            e.x = __expf(v.x-m)*inv; e.y = __expf(v.y-m)*inv;
            e.z = __expf(v.z-m)*inv; e.w = __expf(v.w-m)*inv;
            pb4[jj*32 + l] = e;
        }
        __syncthreads();
        if (t < 128) {
            float4 sm4 = {0.f,0.f,0.f,0.f};
            #pragma unroll
            for (int h = 0; h < 8; h++) {
                float4 p = ((float4*)pbuf[h])[t];
                sm4.x += p.x; sm4.y += p.y; sm4.z += p.z; sm4.w += p.w;
            }
            sm4.x *= 0.125f; sm4.y *= 0.125f; sm4.z *= 0.125f; sm4.w *= 0.125f;
            mo4[c*128 + t] = sm4;
        }
        __syncthreads();
    }
}

// ---------------- HMMA PV: ctx = P @ V, P inline from S, V natural via trans ldsm ---
#define PV_PAD  72
#define PV_PT   (128 * PV_PAD)
#define PV_VT   (64 * PV_PAD)
#define PV_SMEM (((2*PV_PT + 2*PV_VT) * 2) + 1024)
__global__ __launch_bounds__(256)
void pv_mma()
{
    extern __shared__ __nv_bfloat16 smp[];
    __nv_bfloat16* PhT = smp;
    __nv_bfloat16* PlT = smp + PV_PT;
    __nv_bfloat16* VhT = smp + 2*PV_PT;
    __nv_bfloat16* VlT = VhT + PV_VT;
    float2* rstat = (float2*)(smp + 2*PV_PT + 2*PV_VT);

    const int t = threadIdx.x, lane = t & 31, wid = t >> 5;
    const int bh = blockIdx.z, b = bh >> 3, h = bh & 7;
    const int m0 = blockIdx.x * 128;

    const float4* SG  = (const float4*)(g_S + ((size_t)bh*2048 + m0)*2048);
    const uint4*  VhG = (const uint4*)(g_Vh + (size_t)bh*2048*64);
    const uint4*  VlG = (const uint4*)(g_Vl + (size_t)bh*2048*64);

    if (t < 128) rstat[t] = g_stat[bh][m0 + t];

    const int wm = (wid & 3) * 32, wn = (wid >> 2) * 32;
    const int arw = lane & 15, acg = (lane >> 4) * 8;
    const int tkr = ((lane >> 3) & 1) * 8 + (lane & 7);
    const int tnc = (lane >> 4) * 8;
    const uint32_t smb = smem_u32(smp);

    float acc[2][4][4];
    #pragma unroll
    for (int i=0;i<2;i++) for (int j=0;j<4;j++) for (int k=0;k<4;k++) acc[i][j][k]=0.f;

    float4 rs[8];
    uint4 rvh[2], rvl[2];
    #pragma unroll
    for (int it = 0; it < 8; it++) {
        int idx = t + it*256, r = idx >> 4, c4 = idx & 15;
        rs[it] = SG[(size_t)r*512 + c4];
    }
    #pragma unroll
    for (int it = 0; it < 2; it++) {
        int idx = t + it*256;
        rvh[it] = VhG[idx];
        rvl[it] = VlG[idx];
    }
    __syncthreads();

    for (int c = 0; c < 32; c++) {
        #pragma unroll
        for (int it = 0; it < 8; it++) {
            int idx = t + it*256, r = idx >> 4, c4 = idx & 15;
            float2 st = rstat[r];
            float4 s4 = rs[it];
            float e0 = __expf(s4.x - st.x)*st.y;
            float e1 = __expf(s4.y - st.x)*st.y;
            float e2 = __expf(s4.z - st.x)*st.y;
            float e3 = __expf(s4.w - st.x)*st.y;
            __nv_bfloat16 h0=__float2bfloat16_rn(e0), h1=__float2bfloat16_rn(e1);
            __nv_bfloat16 h2=__float2bfloat16_rn(e2), h3=__float2bfloat16_rn(e3);
            __nv_bfloat162* dph = (__nv_bfloat162*)&PhT[r*PV_PAD + c4*4];
            __nv_bfloat162* dpl = (__nv_bfloat162*)&PlT[r*PV_PAD + c4*4];
            dph[0] = __nv_bfloat162(h0,h1); dph[1] = __nv_bfloat162(h2,h3);
            dpl[0] = __nv_bfloat162(__float2bfloat16_rn(e0-__bfloat162float(h0)),
                                    __float2bfloat16_rn(e1-__bfloat162float(h1)));
            dpl[1] = __nv_bfloat162(__float2bfloat16_rn(e2-__bfloat162float(h2)),
                                    __float2bfloat16_rn(e3-__bfloat162float(h3)));
        }
        #pragma unroll
        for (int it = 0; it < 2; it++) {
            int idx = t + it*256, r = idx >> 3, cc = idx & 7;
            ((uint4*)VhT)[r*9 + cc] = rvh[it];
            ((uint4*)VlT)[r*9 + cc] = rvl[it];
        }
        __syncthreads();

        if (c < 31) {
            const int kq4 = (c+1) * 16;
            #pragma unroll
            for (int it = 0; it < 8; it++) {
                int idx = t + it*256, r = idx >> 4, c4 = idx & 15;
                rs[it] = SG[(size_t)r*512 + kq4 + c4];
            }
            #pragma unroll
            for (int it = 0; it < 2; it++) {
                int idx = t + it*256;
                rvh[it] = VhG[(size_t)(c+1)*512 + idx];
                rvl[it] = VlG[(size_t)(c+1)*512 + idx];
            }
        }

        const uint32_t PT2[2] = { smb,               smb + PV_PT*2 };
        const uint32_t VT2[2] = { smb + 2*PV_PT*2,   smb + 2*PV_PT*2 + PV_VT*2 };
        const int tp[3] = {0, 0, 1};
        const int tv[3] = {0, 1, 0};
        #pragma unroll
        for (int p = 0; p < 3; p++) {
            const uint32_t PT = PT2[tp[p]], VT = VT2[tv[p]];
            #pragma unroll
            for (int ks = 0; ks < 4; ks++) {
                uint32_t a[2][4], bfr[4][2];
                #pragma unroll
                for (int mi = 0; mi < 2; mi++) {
                    uint32_t addr = PT + ((wm + mi*16 + arw)*PV_PAD + ks*16 + acg)*2;
                    LDSM_X4(a[mi][0], a[mi][1], a[mi][2], a[mi][3], addr);
                }
                #pragma unroll
                for (int ng = 0; ng < 2; ng++) {
                    uint32_t addr = VT + ((ks*16 + tkr)*PV_PAD + wn + ng*16 + tnc)*2;
                    uint32_t b0,b1,b2,b3;
                    LDSM_X4_T(b0, b1, b2, b3, addr);
                    bfr[ng*2][0]=b0; bfr[ng*2][1]=b1; bfr[ng*2+1][0]=b2; bfr[ng*2+1][1]=b3;
                }
                #pragma unroll
                for (int mi = 0; mi < 2; mi++)
                    #pragma unroll
                    for (int ni = 0; ni < 4; ni++)
                        MMA16816(acc[mi][ni], a[mi], bfr[ni]);
            }
        }
        __syncthreads();
    }

    // epilogue: ctx 2-way split -> g_Ch/g_Cl [m][512]
    #pragma unroll
    for (int mi = 0; mi < 2; mi++) {
        #pragma unroll
        for (int ni = 0; ni < 4; ni++) {
            int row = wm + mi*16 + (lane >> 2);
            int col = wn + ni*8 + (lane & 3)*2;
            size_t ci = ((size_t)(b*2048 + m0 + row))*512 + h*64 + col;
            float d0 = acc[mi][ni][0], d1 = acc[mi][ni][1];
            float d2 = acc[mi][ni][2], d3 = acc[mi][ni][3];
            __nv_bfloat16 h0=__float2bfloat16_rn(d0), h1=__float2bfloat16_rn(d1);
            *(__nv_bfloat162*)&g_Ch[ci] = __nv_bfloat162(h0, h1);
            *(__nv_bfloat162*)&g_Cl[ci] = __nv_bfloat162(
                __float2bfloat16_rn(d0-__bfloat162float(h0)),
                __float2bfloat16_rn(d1-__bfloat162float(h1)));
            __nv_bfloat16 h2=__float2bfloat16_rn(d2), h3=__float2bfloat16_rn(d3);
            *(__nv_bfloat162*)&g_Ch[ci + 8*512] = __nv_bfloat162(h2, h3);
            *(__nv_bfloat162*)&g_Cl[ci + 8*512] = __nv_bfloat162(
                __float2bfloat16_rn(d2-__bfloat162float(h2)),
                __float2bfloat16_rn(d3-__bfloat162float(h3)));
        }
    }
}

// ---------------- launch ----------------
extern "C" void kernel_launch(void* const* d_in, const int* in_sizes, int n_in,
                              void* d_out, int out_size)
{
    const float* Zq   = (const float*)d_in[0];
    const float* Zkv  = (const float*)d_in[1];
    const float* mask = (const float*)d_in[2];
    const float* Wqkv = (const float*)d_in[3];
    const float* Wout = (const float*)d_in[4];
    float* out   = (float*)d_out;
    float* meanp = out + (size_t)B_ * S_ * D_;

    __nv_bfloat16 *Xqh,*Xql,*Xkh,*Xkl,*Wh,*Wl,*Woh,*Wol,*Ch,*Cl;
    cudaGetSymbolAddress((void**)&Xqh, g_Xqh); cudaGetSymbolAddress((void**)&Xql, g_Xql);
    cudaGetSymbolAddress((void**)&Xkh, g_Xkh); cudaGetSymbolAddress((void**)&Xkl, g_Xkl);
    cudaGetSymbolAddress((void**)&Wh,  g_Wh);  cudaGetSymbolAddress((void**)&Wl,  g_Wl);
    cudaGetSymbolAddress((void**)&Woh, g_Woh); cudaGetSymbolAddress((void**)&Wol, g_Wol);
    cudaGetSymbolAddress((void**)&Ch,  g_Ch);  cudaGetSymbolAddress((void**)&Cl,  g_Cl);

    cudaFuncSetAttribute(scores_mma,  cudaFuncAttributeMaxDynamicSharedMemorySize, SC_SMEM);
    cudaFuncSetAttribute(pv_mma,      cudaFuncAttributeMaxDynamicSharedMemorySize, PV_SMEM);
    cudaFuncSetAttribute(hmma_proj<0>, cudaFuncAttributeMaxDynamicSharedMemorySize, PR_SMEM);
    cudaFuncSetAttribute(hmma_proj<1>, cudaFuncAttributeMaxDynamicSharedMemorySize, PR_SMEM);
    cudaFuncSetAttribute(hmma_proj<2>, cudaFuncAttributeMaxDynamicSharedMemorySize, PR_SMEM);

    // input 2-way splits
    split2<<<4096, 256>>>((const float4*)Zq,  (__nv_bfloat162*)Xqh, (__nv_bfloat162*)Xql);
    split2<<<4096, 256>>>((const float4*)Zkv, (__nv_bfloat162*)Xkh, (__nv_bfloat162*)Xkl);
    split2<<<768,  256>>>((const float4*)Wqkv,(__nv_bfloat162*)Wh,  (__nv_bfloat162*)Wl);
    split2<<<256,  256>>>((const float4*)Wout,(__nv_bfloat162*)Woh, (__nv_bfloat162*)Wol);

    // projections via HMMA (3-term)
    hmma_proj<1><<<dim3(4, 64), 256, PR_SMEM>>>(Xqh, Xql, Wh, Wl, nullptr, 1536);
    hmma_proj<2><<<dim3(8, 64), 256, PR_SMEM>>>(Xkh, Xkl, Wh + 512, Wl + 512, nullptr, 1536);

    // scores via HMMA (6-term), fused mask + chunk softmax stats
    scores_mma<<<dim3(16, 16, 32), 256, SC_SMEM>>>(mask);

    // fold chunk stats
    combine_stats<<<dim3(8, 32), 256>>>();

    // single-pass mean over heads
    softmax_mean_k<<<dim3(S_, B_), 256>>>(meanp);

    // ctx = P @ V via HMMA (3-term), P inline from S; epilogue stores ctx splits
    pv_mma<<<dim3(16, 1, 32), 256, PV_SMEM>>>();

    // out = ctx @ Wout via HMMA (3-term)
    hmma_proj<0><<<dim3(4, 64), 256, PR_SMEM>>>(Ch, Cl, Woh, Wol, out, 512);
}

// round 15
// speedup vs baseline: 6.5658x; 1.1206x over previous
#include <cuda_runtime.h>
#include <cuda_bf16.h>
#include <cstdint>

#define B_   4
#define S_   2048
#define D_   512
#define H_   8
#define DK_  64
#define SCALE_ 0.125f

#define NQK ((size_t)B_*H_*S_*DK_)
#define NSS ((size_t)B_*H_*S_*S_)
#define NMD ((size_t)B_*S_*D_)

// ---------------- scratch ----------------
__device__ __nv_bfloat16 g_Xqh[NMD], g_Xql[NMD];           // Zq  [m][512] splits
__device__ __nv_bfloat16 g_Xkh[NMD], g_Xkl[NMD];           // Zkv [m][512] splits
__device__ __nv_bfloat16 g_Wh[512*1536], g_Wl[512*1536];   // Wqkv [k][n] splits
__device__ __nv_bfloat16 g_Woh[512*512], g_Wol[512*512];   // Wout [k][n] splits
__device__ __nv_bfloat16 g_Qh[NQK], g_Ql[NQK];             // [bh][s][64] 2-way
__device__ __nv_bfloat16 g_Kh[NQK], g_Kl[NQK];
__device__ __nv_bfloat16 g_Vh[NQK], g_Vl[NQK];
__device__ __nv_bfloat16 g_Ch[NMD], g_Cl[NMD];             // ctx splits [m][512]
__device__ float         g_S[NSS];                          // masked, scaled scores
__device__ float2        g_cstat[32][16][2048];
__device__ float2        g_stat[32][2048];

// ---------------- helpers ----------------
__device__ __forceinline__ uint32_t smem_u32(const void* p){
    uint32_t a; asm("{ .reg .u64 t; cvta.to.shared.u64 t,%1; cvt.u32.u64 %0,t; }":"=r"(a):"l"(p)); return a;
}
#define LDSM_X4(r0,r1,r2,r3,addr) \
    asm volatile("ldmatrix.sync.aligned.m8n8.x4.shared.b16 {%0,%1,%2,%3},[%4];" \
        :"=r"(r0),"=r"(r1),"=r"(r2),"=r"(r3):"r"(addr))
#define LDSM_X4_T(r0,r1,r2,r3,addr) \
    asm volatile("ldmatrix.sync.aligned.m8n8.x4.trans.shared.b16 {%0,%1,%2,%3},[%4];" \
        :"=r"(r0),"=r"(r1),"=r"(r2),"=r"(r3):"r"(addr))
#define MMA16816(d,a,b) \
    asm volatile("mma.sync.aligned.m16n8k16.row.col.f32.bf16.bf16.f32 " \
        "{%0,%1,%2,%3},{%4,%5,%6,%7},{%8,%9},{%0,%1,%2,%3};" \
        : "+f"((d)[0]),"+f"((d)[1]),"+f"((d)[2]),"+f"((d)[3]) \
        : "r"((a)[0]),"r"((a)[1]),"r"((a)[2]),"r"((a)[3]),"r"((b)[0]),"r"((b)[1]))

__device__ __forceinline__ void split2v(float v, __nv_bfloat16& h, __nv_bfloat16& l){
    h = __float2bfloat16_rn(v);
    l = __float2bfloat16_rn(v - __bfloat162float(h));
}

// ---------------- elementwise 2-way split ----------------
__global__ __launch_bounds__(256)
void split2(const float4* __restrict__ src, __nv_bfloat162* __restrict__ h2,
            __nv_bfloat162* __restrict__ l2)
{
    size_t i = (size_t)blockIdx.x * 256 + threadIdx.x;
    float4 v = src[i];
    __nv_bfloat16 h0=__float2bfloat16_rn(v.x), h1=__float2bfloat16_rn(v.y);
    __nv_bfloat16 h2v=__float2bfloat16_rn(v.z), h3=__float2bfloat16_rn(v.w);
    h2[2*i]   = __nv_bfloat162(h0,h1);
    h2[2*i+1] = __nv_bfloat162(h2v,h3);
    l2[2*i]   = __nv_bfloat162(__float2bfloat16_rn(v.x-__bfloat162float(h0)),
                               __float2bfloat16_rn(v.y-__bfloat162float(h1)));
    l2[2*i+1] = __nv_bfloat162(__float2bfloat16_rn(v.z-__bfloat162float(h2v)),
                               __float2bfloat16_rn(v.w-__bfloat162float(h3)));
}

// ---------------- HMMA projection GEMM: C = (Ah+Al) @ (Bh+Bl), K=512 ----------------
// 3-term: AhBh + AhBl + AlBh. A [m][512] splits, B [k][n] row-major splits (trans ldsm).
// MODE 0: plain fp32 store (ldc=512). MODE 1: Q 2-way split. MODE 2: K/V 2-way splits.
#define PR_A   (128*72)
#define PR_B   (64*136)
#define PR_SMEM ((2*PR_A + 2*PR_B)*2)
template<int MODE>
__global__ __launch_bounds__(256)
void hmma_proj(const __nv_bfloat16* __restrict__ Ah_, const __nv_bfloat16* __restrict__ Al_,
               const __nv_bfloat16* __restrict__ Bh_, const __nv_bfloat16* __restrict__ Bl_,
               float* __restrict__ C, int ldb)
{
    extern __shared__ __nv_bfloat16 smb[];
    __nv_bfloat16* AhT = smb;
    __nv_bfloat16* AlT = smb + PR_A;
    __nv_bfloat16* BhT = smb + 2*PR_A;
    __nv_bfloat16* BlT = BhT + PR_B;

    const int t = threadIdx.x, lane = t & 31, wid = t >> 5;
    const int m0 = blockIdx.y * 128, n0 = blockIdx.x * 128;
    const int ldb4 = ldb >> 3, n04 = n0 >> 3;

    const uint4* AhG = (const uint4*)Ah_;
    const uint4* AlG = (const uint4*)Al_;
    const uint4* BhG = (const uint4*)Bh_;
    const uint4* BlG = (const uint4*)Bl_;

    const int wm = (wid & 1) * 64, wn = (wid >> 1) * 32;
    const int arw = lane & 15, acg = (lane >> 4) * 8;
    const int tkr = ((lane >> 3) & 1) * 8 + (lane & 7);
    const int tnc = (lane >> 4) * 8;
    const uint32_t smba = smem_u32(smb);

    float acc[4][4][4];
    #pragma unroll
    for (int i=0;i<4;i++) for (int j=0;j<4;j++) for (int k=0;k<4;k++) acc[i][j][k]=0.f;

    for (int c = 0; c < 8; c++) {
        if (c) __syncthreads();
        #pragma unroll
        for (int it = 0; it < 4; it++) {
            int idx = t + it*256, r = idx >> 3, cc = idx & 7;
            size_t si = (size_t)(m0 + r)*64 + c*8 + cc;
            ((uint4*)AhT)[r*9 + cc] = AhG[si];
            ((uint4*)AlT)[r*9 + cc] = AlG[si];
        }
        #pragma unroll
        for (int it = 0; it < 4; it++) {
            int idx = t + it*256, r = idx >> 4, cc = idx & 15;
            size_t si = (size_t)(c*64 + r)*ldb4 + n04 + cc;
            ((uint4*)BhT)[r*17 + cc] = BhG[si];
            ((uint4*)BlT)[r*17 + cc] = BlG[si];
        }
        __syncthreads();

        const uint32_t AT2[2] = { smba, smba + PR_A*2 };
        const uint32_t BT2[2] = { smba + 2*PR_A*2, smba + 2*PR_A*2 + PR_B*2 };
        const int ta[3] = {0,0,1};
        const int tb[3] = {0,1,0};
        #pragma unroll
        for (int p = 0; p < 3; p++) {
            const uint32_t AT = AT2[ta[p]], BT = BT2[tb[p]];
            #pragma unroll
            for (int ks = 0; ks < 4; ks++) {
                uint32_t a[4][4], bfr[4][2];
                #pragma unroll
                for (int mi = 0; mi < 4; mi++) {
                    uint32_t addr = AT + ((wm + mi*16 + arw)*72 + ks*16 + acg)*2;
                    LDSM_X4(a[mi][0], a[mi][1], a[mi][2], a[mi][3], addr);
                }
                #pragma unroll
                for (int ng = 0; ng < 2; ng++) {
                    uint32_t addr = BT + ((ks*16 + tkr)*136 + wn + ng*16 + tnc)*2;
                    uint32_t b0,b1,b2,b3;
                    LDSM_X4_T(b0, b1, b2, b3, addr);
                    bfr[ng*2][0]=b0; bfr[ng*2][1]=b1; bfr[ng*2+1][0]=b2; bfr[ng*2+1][1]=b3;
                }
                #pragma unroll
                for (int mi = 0; mi < 4; mi++)
                    #pragma unroll
                    for (int ni = 0; ni < 4; ni++)
                        MMA16816(acc[mi][ni], a[mi], bfr[ni]);
            }
        }
    }

    // ---- epilogue ----
    #pragma unroll
    for (int mi = 0; mi < 4; mi++) {
        #pragma unroll
        for (int ni = 0; ni < 4; ni++) {
            const int row = m0 + wm + mi*16 + (lane >> 2);
            const int col = wn + ni*8 + (lane & 3)*2;
            float d0 = acc[mi][ni][0], d1 = acc[mi][ni][1];
            float d2 = acc[mi][ni][2], d3 = acc[mi][ni][3];
            if (MODE == 0) {
                *(float2*)&C[(size_t)row*512 + n0 + col]     = make_float2(d0, d1);
                *(float2*)&C[(size_t)(row+8)*512 + n0 + col] = make_float2(d2, d3);
            } else {
                const int gn = n0 + col;
                const int b = row >> 11, s = row & 2047;
                __nv_bfloat16 *ph, *pl;
                int gnm;
                if (MODE == 1)      { ph = g_Qh; pl = g_Ql; gnm = gn; }
                else if (gn < 512)  { ph = g_Kh; pl = g_Kl; gnm = gn; }
                else                { ph = g_Vh; pl = g_Vl; gnm = gn - 512; }
                const int hh = gnm >> 6, dk = gnm & 63;
                size_t base = ((size_t)((b<<3)+hh)*2048 + s)*64 + dk;
                __nv_bfloat16 xh0,xl0,xh1,xl1;
                split2v(d0, xh0, xl0); split2v(d1, xh1, xl1);
                *(__nv_bfloat162*)&ph[base] = __nv_bfloat162(xh0, xh1);
                *(__nv_bfloat162*)&pl[base] = __nv_bfloat162(xl0, xl1);
                split2v(d2, xh0, xl0); split2v(d3, xh1, xl1);
                *(__nv_bfloat162*)&ph[base+512] = __nv_bfloat162(xh0, xh1);
                *(__nv_bfloat162*)&pl[base+512] = __nv_bfloat162(xl0, xl1);
            }
        }
    }
}

// ---------------- HMMA scores (3-term): S = QK^T*SCALE + mask, + chunk stats ----
#define SC_PAD   72
#define SC_TILE  (128 * SC_PAD)
#define SC_SMEM  (4 * SC_TILE * 2)
__global__ __launch_bounds__(256)
void scores_mma(const float* __restrict__ maskp)
{
    extern __shared__ __nv_bfloat16 smt[];
    const int t = threadIdx.x, lane = t & 31, wid = t >> 5;
    const int bh = blockIdx.z, m0 = blockIdx.y * 128, n0 = blockIdx.x * 128;

    {
        const size_t qoff = ((size_t)bh*2048 + m0)*64;
        const size_t koff = ((size_t)bh*2048 + n0)*64;
        const __nv_bfloat16* gsrc[4] = { g_Qh+qoff, g_Ql+qoff, g_Kh+koff, g_Kl+koff };
        #pragma unroll
        for (int tl = 0; tl < 4; tl++) {
            const uint4* src = (const uint4*)gsrc[tl];
            uint4* dst = (uint4*)(smt + tl*SC_TILE);
            #pragma unroll
            for (int it = 0; it < 4; it++) {
                int idx = t + it*256;
                int r = idx >> 3, cc = idx & 7;
                dst[r*9 + cc] = src[r*8 + cc];
            }
        }
    }
    __syncthreads();

    const int wm = (wid & 1) * 64, wn = (wid >> 1) * 32;
    const int arw = lane & 15, acg = (lane >> 4) * 8;
    const int brw = ((lane >> 4) << 3) + (lane & 7), bcg = ((lane >> 3) & 1) * 8;

    float acc[4][4][4];
    #pragma unroll
    for (int i=0;i<4;i++) for (int j=0;j<4;j++) for (int k=0;k<4;k++) acc[i][j][k]=0.f;

    const int pq[3] = {0,0,1};
    const int pk[3] = {0,1,0};
    const uint32_t smb = smem_u32(smt);

    #pragma unroll
    for (int p = 0; p < 3; p++) {
        const uint32_t QT = smb + pq[p]*SC_TILE*2;
        const uint32_t KT = smb + (2+pk[p])*SC_TILE*2;
        #pragma unroll
        for (int ks = 0; ks < 4; ks++) {
            uint32_t a[4][4], bfr[4][2];
            #pragma unroll
            for (int mi = 0; mi < 4; mi++) {
                uint32_t addr = QT + ((wm + mi*16 + arw)*SC_PAD + ks*16 + acg)*2;
                LDSM_X4(a[mi][0], a[mi][1], a[mi][2], a[mi][3], addr);
            }
            #pragma unroll
            for (int ng = 0; ng < 2; ng++) {
                uint32_t addr = KT + ((wn + ng*16 + brw)*SC_PAD + ks*16 + bcg)*2;
                uint32_t b0,b1,b2,b3;
                LDSM_X4(b0, b1, b2, b3, addr);
                bfr[ng*2][0]=b0; bfr[ng*2][1]=b1; bfr[ng*2+1][0]=b2; bfr[ng*2+1][1]=b3;
            }
            #pragma unroll
            for (int mi = 0; mi < 4; mi++)
                #pragma unroll
                for (int ni = 0; ni < 4; ni++)
                    MMA16816(acc[mi][ni], a[mi], bfr[ni]);
        }
    }

    __syncthreads();
    float2* wstat = (float2*)smt;

    float rm[8], rsum[8];
    #pragma unroll
    for (int mi = 0; mi < 4; mi++) {
        const int grow0 = m0 + wm + mi*16 + (lane>>2);
        #pragma unroll
        for (int ni = 0; ni < 4; ni++) {
            const int col = n0 + wn + ni*8 + (lane&3)*2;
            float2 mk0 = *(const float2*)&maskp[(size_t)grow0*2048 + col];
            float2 mk1 = *(const float2*)&maskp[(size_t)(grow0+8)*2048 + col];
            acc[mi][ni][0] = acc[mi][ni][0]*SCALE_ + mk0.x;
            acc[mi][ni][1] = acc[mi][ni][1]*SCALE_ + mk0.y;
            acc[mi][ni][2] = acc[mi][ni][2]*SCALE_ + mk1.x;
            acc[mi][ni][3] = acc[mi][ni][3]*SCALE_ + mk1.y;
        }
        float m0v = -1e30f, m1v = -1e30f;
        #pragma unroll
        for (int ni = 0; ni < 4; ni++) {
            m0v = fmaxf(m0v, fmaxf(acc[mi][ni][0], acc[mi][ni][1]));
            m1v = fmaxf(m1v, fmaxf(acc[mi][ni][2], acc[mi][ni][3]));
        }
        m0v = fmaxf(m0v, __shfl_xor_sync(0xffffffffu, m0v, 1));
        m0v = fmaxf(m0v, __shfl_xor_sync(0xffffffffu, m0v, 2));
        m1v = fmaxf(m1v, __shfl_xor_sync(0xffffffffu, m1v, 1));
        m1v = fmaxf(m1v, __shfl_xor_sync(0xffffffffu, m1v, 2));
        float s0 = 0.f, s1 = 0.f;
        #pragma unroll
        for (int ni = 0; ni < 4; ni++) {
            s0 += __expf(acc[mi][ni][0]-m0v) + __expf(acc[mi][ni][1]-m0v);
            s1 += __expf(acc[mi][ni][2]-m1v) + __expf(acc[mi][ni][3]-m1v);
        }
        s0 += __shfl_xor_sync(0xffffffffu, s0, 1);
        s0 += __shfl_xor_sync(0xffffffffu, s0, 2);
        s1 += __shfl_xor_sync(0xffffffffu, s1, 1);
        s1 += __shfl_xor_sync(0xffffffffu, s1, 2);
        rm[mi*2]=m0v; rsum[mi*2]=s0; rm[mi*2+1]=m1v; rsum[mi*2+1]=s1;
    }
    if ((lane & 3) == 0) {
        #pragma unroll
        for (int mi = 0; mi < 4; mi++) {
            int r = wm + mi*16 + (lane>>2);
            wstat[r*4 + (wid>>1)]     = make_float2(rm[mi*2],   rsum[mi*2]);
            wstat[(r+8)*4 + (wid>>1)] = make_float2(rm[mi*2+1], rsum[mi*2+1]);
        }
    }
    __syncthreads();
    if (t < 128) {
        float2 a = wstat[t*4+0], b2 = wstat[t*4+1], c2 = wstat[t*4+2], d2 = wstat[t*4+3];
        float m = fmaxf(fmaxf(a.x,b2.x), fmaxf(c2.x,d2.x));
        float s = a.y*__expf(a.x-m) + b2.y*__expf(b2.x-m)
                + c2.y*__expf(c2.x-m) + d2.y*__expf(d2.x-m);
        g_cstat[bh][n0>>7][m0+t] = make_float2(m, s);
    }

    float* Crow = g_S + (size_t)bh*2048*2048;
    #pragma unroll
    for (int mi = 0; mi < 4; mi++) {
        #pragma unroll
        for (int ni = 0; ni < 4; ni++) {
            int row = m0 + wm + mi*16 + (lane >> 2);
            int col = n0 + wn + ni*8 + (lane & 3)*2;
            float2 v0 = { acc[mi][ni][0], acc[mi][ni][1] };
            float2 v1 = { acc[mi][ni][2], acc[mi][ni][3] };
            *(float2*)&Crow[(size_t)row*2048 + col]     = v0;
            *(float2*)&Crow[(size_t)(row+8)*2048 + col] = v1;
        }
    }
}

// ---------------- combine chunk stats -> (max, 1/sum) per row ----------------
__global__ __launch_bounds__(256)
void combine_stats()
{
    const int bh = blockIdx.y;
    const int r  = blockIdx.x * 256 + threadIdx.x;
    float2 v[16];
    float m = -1e30f;
    #pragma unroll
    for (int c = 0; c < 16; c++) { v[c] = g_cstat[bh][c][r]; m = fmaxf(m, v[c].x); }
    float s = 0.f;
    #pragma unroll
    for (int c = 0; c < 16; c++) s += v[c].y * __expf(v[c].x - m);
    g_stat[bh][r] = make_float2(m, 1.f / s);
}

// ---------------- single-pass mean over heads ----------------
__global__ __launch_bounds__(256)
void softmax_mean_k(float* __restrict__ mean_out)
{
    __shared__ __align__(16) float pbuf[8][512];

    const int t = threadIdx.x, w = t >> 5, l = t & 31;
    const int q = blockIdx.x, b = blockIdx.y;

    const float2 st = g_stat[b*8 + w][q];
    const float m = st.x, inv = st.y;

    const size_t rbase = ((size_t)(b*8 + w)*2048 + q)*2048;
    const float4* rowv = (const float4*)(g_S + rbase);
    float4* pb4 = (float4*)pbuf[w];
    float4* mo4 = (float4*)(mean_out + (size_t)(b*2048 + q)*2048);

    for (int c = 0; c < 4; c++) {
        #pragma unroll
        for (int jj = 0; jj < 4; jj++) {
            int j = c*128 + jj*32 + l;
            float4 v = rowv[j], e;
            e.x = __expf(v.x-m)*inv; e.y = __expf(v.y-m)*inv;
            e.z = __expf(v.z-m)*inv; e.w = __expf(v.w-m)*inv;
            pb4[jj*32 + l] = e;
        }
        __syncthreads();
        if (t < 128) {
            float4 sm4 = {0.f,0.f,0.f,0.f};
            #pragma unroll
            for (int h = 0; h < 8; h++) {
                float4 p = ((float4*)pbuf[h])[t];
                sm4.x += p.x; sm4.y += p.y; sm4.z += p.z; sm4.w += p.w;
            }
            sm4.x *= 0.125f; sm4.y *= 0.125f; sm4.z *= 0.125f; sm4.w *= 0.125f;
            mo4[c*128 + t] = sm4;
        }
        __syncthreads();
    }
}

// ---------------- HMMA PV: ctx = P @ V, P inline from S, V natural via trans ldsm ---
#define PV_PAD  72
#define PV_PT   (128 * PV_PAD)
#define PV_VT   (64 * PV_PAD)
#define PV_SMEM (((2*PV_PT + 2*PV_VT) * 2) + 1024)
__global__ __launch_bounds__(256)
void pv_mma()
{
    extern __shared__ __nv_bfloat16 smp[];
    __nv_bfloat16* PhT = smp;
    __nv_bfloat16* PlT = smp + PV_PT;
    __nv_bfloat16* VhT = smp + 2*PV_PT;
    __nv_bfloat16* VlT = VhT + PV_VT;
    float2* rstat = (float2*)(smp + 2*PV_PT + 2*PV_VT);

    const int t = threadIdx.x, lane = t & 31, wid = t >> 5;
    const int bh = blockIdx.z, b = bh >> 3, h = bh & 7;
    const int m0 = blockIdx.x * 128;

    const float4* SG  = (const float4*)(g_S + ((size_t)bh*2048 + m0)*2048);
    const uint4*  VhG = (const uint4*)(g_Vh + (size_t)bh*2048*64);
    const uint4*  VlG = (const uint4*)(g_Vl + (size_t)bh*2048*64);

    if (t < 128) rstat[t] = g_stat[bh][m0 + t];

    const int wm = (wid & 3) * 32, wn = (wid >> 2) * 32;
    const int arw = lane & 15, acg = (lane >> 4) * 8;
    const int tkr = ((lane >> 3) & 1) * 8 + (lane & 7);
    const int tnc = (lane >> 4) * 8;
    const uint32_t smb = smem_u32(smp);

    float acc[2][4][4];
    #pragma unroll
    for (int i=0;i<2;i++) for (int j=0;j<4;j++) for (int k=0;k<4;k++) acc[i][j][k]=0.f;

    float4 rs[8];
    uint4 rvh[2], rvl[2];
    #pragma unroll
    for (int it = 0; it < 8; it++) {
        int idx = t + it*256, r = idx >> 4, c4 = idx & 15;
        rs[it] = SG[(size_t)r*512 + c4];
    }
    #pragma unroll
    for (int it = 0; it < 2; it++) {
        int idx = t + it*256;
        rvh[it] = VhG[idx];
        rvl[it] = VlG[idx];
    }
    __syncthreads();

    for (int c = 0; c < 32; c++) {
        #pragma unroll
        for (int it = 0; it < 8; it++) {
            int idx = t + it*256, r = idx >> 4, c4 = idx & 15;
            float2 st = rstat[r];
            float4 s4 = rs[it];
            float e0 = __expf(s4.x - st.x)*st.y;
            float e1 = __expf(s4.y - st.x)*st.y;
            float e2 = __expf(s4.z - st.x)*st.y;
            float e3 = __expf(s4.w - st.x)*st.y;
            __nv_bfloat16 h0=__float2bfloat16_rn(e0), h1=__float2bfloat16_rn(e1);
            __nv_bfloat16 h2=__float2bfloat16_rn(e2), h3=__float2bfloat16_rn(e3);
            __nv_bfloat162* dph = (__nv_bfloat162*)&PhT[r*PV_PAD + c4*4];
            __nv_bfloat162* dpl = (__nv_bfloat162*)&PlT[r*PV_PAD + c4*4];
            dph[0] = __nv_bfloat162(h0,h1); dph[1] = __nv_bfloat162(h2,h3);
            dpl[0] = __nv_bfloat162(__float2bfloat16_rn(e0-__bfloat162float(h0)),
                                    __float2bfloat16_rn(e1-__bfloat162float(h1)));
            dpl[1] = __nv_bfloat162(__float2bfloat16_rn(e2-__bfloat162float(h2)),
                                    __float2bfloat16_rn(e3-__bfloat162float(h3)));
        }
        #pragma unroll
        for (int it = 0; it < 2; it++) {
            int idx = t + it*256, r = idx >> 3, cc = idx & 7;
            ((uint4*)VhT)[r*9 + cc] = rvh[it];
            ((uint4*)VlT)[r*9 + cc] = rvl[it];
        }
        __syncthreads();

        if (c < 31) {
            const int kq4 = (c+1) * 16;
            #pragma unroll
            for (int it = 0; it < 8; it++) {
                int idx = t + it*256, r = idx >> 4, c4 = idx & 15;
                rs[it] = SG[(size_t)r*512 + kq4 + c4];
            }
            #pragma unroll
            for (int it = 0; it < 2; it++) {
                int idx = t + it*256;
                rvh[it] = VhG[(size_t)(c+1)*512 + idx];
                rvl[it] = VlG[(size_t)(c+1)*512 + idx];
            }
        }

        const uint32_t PT2[2] = { smb,               smb + PV_PT*2 };
        const uint32_t VT2[2] = { smb + 2*PV_PT*2,   smb + 2*PV_PT*2 + PV_VT*2 };
        const int tp[3] = {0, 0, 1};
        const int tv[3] = {0, 1, 0};
        #pragma unroll
        for (int p = 0; p < 3; p++) {
            const uint32_t PT = PT2[tp[p]], VT = VT2[tv[p]];
            #pragma unroll
            for (int ks = 0; ks < 4; ks++) {
                uint32_t a[2][4], bfr[4][2];
                #pragma unroll
                for (int mi = 0; mi < 2; mi++) {
                    uint32_t addr = PT + ((wm + mi*16 + arw)*PV_PAD + ks*16 + acg)*2;
                    LDSM_X4(a[mi][0], a[mi][1], a[mi][2], a[mi][3], addr);
                }
                #pragma unroll
                for (int ng = 0; ng < 2; ng++) {
                    uint32_t addr = VT + ((ks*16 + tkr)*PV_PAD + wn + ng*16 + tnc)*2;
                    uint32_t b0,b1,b2,b3;
                    LDSM_X4_T(b0, b1, b2, b3, addr);
                    bfr[ng*2][0]=b0; bfr[ng*2][1]=b1; bfr[ng*2+1][0]=b2; bfr[ng*2+1][1]=b3;
                }
                #pragma unroll
                for (int mi = 0; mi < 2; mi++)
                    #pragma unroll
                    for (int ni = 0; ni < 4; ni++)
                        MMA16816(acc[mi][ni], a[mi], bfr[ni]);
            }
        }
        __syncthreads();
    }

    // epilogue: ctx 2-way split -> g_Ch/g_Cl [m][512]
    #pragma unroll
    for (int mi = 0; mi < 2; mi++) {
        #pragma unroll
        for (int ni = 0; ni < 4; ni++) {
            int row = wm + mi*16 + (lane >> 2);
            int col = wn + ni*8 + (lane & 3)*2;
            size_t ci = ((size_t)(b*2048 + m0 + row))*512 + h*64 + col;
            float d0 = acc[mi][ni][0], d1 = acc[mi][ni][1];
            float d2 = acc[mi][ni][2], d3 = acc[mi][ni][3];
            __nv_bfloat16 h0=__float2bfloat16_rn(d0), h1=__float2bfloat16_rn(d1);
            *(__nv_bfloat162*)&g_Ch[ci] = __nv_bfloat162(h0, h1);
            *(__nv_bfloat162*)&g_Cl[ci] = __nv_bfloat162(
                __float2bfloat16_rn(d0-__bfloat162float(h0)),
                __float2bfloat16_rn(d1-__bfloat162float(h1)));
            __nv_bfloat16 h2=__float2bfloat16_rn(d2), h3=__float2bfloat16_rn(d3);
            *(__nv_bfloat162*)&g_Ch[ci + 8*512] = __nv_bfloat162(h2, h3);
            *(__nv_bfloat162*)&g_Cl[ci + 8*512] = __nv_bfloat162(
                __float2bfloat16_rn(d2-__bfloat162float(h2)),
                __float2bfloat16_rn(d3-__bfloat162float(h3)));
        }
    }
}

// ---------------- launch ----------------
extern "C" void kernel_launch(void* const* d_in, const int* in_sizes, int n_in,
                              void* d_out, int out_size)
{
    const float* Zq   = (const float*)d_in[0];
    const float* Zkv  = (const float*)d_in[1];
    const float* mask = (const float*)d_in[2];
    const float* Wqkv = (const float*)d_in[3];
    const float* Wout = (const float*)d_in[4];
    float* out   = (float*)d_out;
    float* meanp = out + (size_t)B_ * S_ * D_;

    __nv_bfloat16 *Xqh,*Xql,*Xkh,*Xkl,*Wh,*Wl,*Woh,*Wol,*Ch,*Cl;
    cudaGetSymbolAddress((void**)&Xqh, g_Xqh); cudaGetSymbolAddress((void**)&Xql, g_Xql);
    cudaGetSymbolAddress((void**)&Xkh, g_Xkh); cudaGetSymbolAddress((void**)&Xkl, g_Xkl);
    cudaGetSymbolAddress((void**)&Wh,  g_Wh);  cudaGetSymbolAddress((void**)&Wl,  g_Wl);
    cudaGetSymbolAddress((void**)&Woh, g_Woh); cudaGetSymbolAddress((void**)&Wol, g_Wol);
    cudaGetSymbolAddress((void**)&Ch,  g_Ch);  cudaGetSymbolAddress((void**)&Cl,  g_Cl);

    cudaFuncSetAttribute(scores_mma,  cudaFuncAttributeMaxDynamicSharedMemorySize, SC_SMEM);
    cudaFuncSetAttribute(pv_mma,      cudaFuncAttributeMaxDynamicSharedMemorySize, PV_SMEM);
    cudaFuncSetAttribute(hmma_proj<0>, cudaFuncAttributeMaxDynamicSharedMemorySize, PR_SMEM);
    cudaFuncSetAttribute(hmma_proj<1>, cudaFuncAttributeMaxDynamicSharedMemorySize, PR_SMEM);
    cudaFuncSetAttribute(hmma_proj<2>, cudaFuncAttributeMaxDynamicSharedMemorySize, PR_SMEM);

    // input 2-way splits
    split2<<<4096, 256>>>((const float4*)Zq,  (__nv_bfloat162*)Xqh, (__nv_bfloat162*)Xql);
    split2<<<4096, 256>>>((const float4*)Zkv, (__nv_bfloat162*)Xkh, (__nv_bfloat162*)Xkl);
    split2<<<768,  256>>>((const float4*)Wqkv,(__nv_bfloat162*)Wh,  (__nv_bfloat162*)Wl);
    split2<<<256,  256>>>((const float4*)Wout,(__nv_bfloat162*)Woh, (__nv_bfloat162*)Wol);

    // projections via HMMA (3-term)
    hmma_proj<1><<<dim3(4, 64), 256, PR_SMEM>>>(Xqh, Xql, Wh, Wl, nullptr, 1536);
    hmma_proj<2><<<dim3(8, 64), 256, PR_SMEM>>>(Xkh, Xkl, Wh + 512, Wl + 512, nullptr, 1536);

    // scores via HMMA (3-term), fused mask + chunk softmax stats
    scores_mma<<<dim3(16, 16, 32), 256, SC_SMEM>>>(mask);

    // fold chunk stats
    combine_stats<<<dim3(8, 32), 256>>>();

    // single-pass mean over heads
    softmax_mean_k<<<dim3(S_, B_), 256>>>(meanp);

    // ctx = P @ V via HMMA (3-term), P inline from S; epilogue stores ctx splits
    pv_mma<<<dim3(16, 1, 32), 256, PV_SMEM>>>();

    // out = ctx @ Wout via HMMA (3-term)
    hmma_proj<0><<<dim3(4, 64), 256, PR_SMEM>>>(Ch, Cl, Woh, Wol, out, 512);
}